// round 1
// baseline (speedup 1.0000x reference)
#include <cuda_runtime.h>
#include <math.h>

// Problem shape (fixed)
#define BATCH 4
#define SEQ   2048
#define EMB   2048
#define DIM   2048

// GEMM tiling
#define BM 128
#define BN 128
#define BK 8
#define TM 8
#define TN 8
#define PAD 4
#define NTHREADS 256

// Scratch (no cudaMalloc allowed): Q, K, V projections + scores/attn buffer.
__device__ float g_Q[(size_t)BATCH * SEQ * DIM];
__device__ float g_K[(size_t)BATCH * SEQ * DIM];
__device__ float g_V[(size_t)BATCH * SEQ * DIM];
__device__ float g_S[(size_t)BATCH * SEQ * SEQ];

// ---------------------------------------------------------------------------
// TN GEMM: C[M,N] = A[M,K] * B[N,K]^T, both operands K-contiguous (row-major).
// Used for the QKV projections (A = x flattened [B*S, E], B = W [D, E]).
// Dims are exact multiples of the tile sizes; no bounds checks.
// ---------------------------------------------------------------------------
__global__ __launch_bounds__(NTHREADS, 2)
void gemm_tn_kernel(const float* __restrict__ A, const float* __restrict__ B,
                    float* __restrict__ C, int N, int K)
{
    __shared__ float As[BK][BM + PAD];
    __shared__ float Bs[BK][BN + PAD];

    const int tid = threadIdx.x;
    const int tx = tid & 15;
    const int ty = tid >> 4;

    const float* Ab = A + (size_t)blockIdx.y * BM * K;
    const float* Bb = B + (size_t)blockIdx.x * BN * K;

    const int lrow = tid >> 1;        // 0..127
    const int lk4  = (tid & 1) * 4;   // 0 or 4

    float acc[TM][TN] = {};

    for (int k0 = 0; k0 < K; k0 += BK) {
        float4 av = *(const float4*)(Ab + (size_t)lrow * K + k0 + lk4);
        float4 bv = *(const float4*)(Bb + (size_t)lrow * K + k0 + lk4);
        As[lk4 + 0][lrow] = av.x; As[lk4 + 1][lrow] = av.y;
        As[lk4 + 2][lrow] = av.z; As[lk4 + 3][lrow] = av.w;
        Bs[lk4 + 0][lrow] = bv.x; Bs[lk4 + 1][lrow] = bv.y;
        Bs[lk4 + 2][lrow] = bv.z; Bs[lk4 + 3][lrow] = bv.w;
        __syncthreads();

#pragma unroll
        for (int kk = 0; kk < BK; ++kk) {
            float a[TM], b[TN];
            *(float4*)&a[0] = *(const float4*)&As[kk][ty * TM];
            *(float4*)&a[4] = *(const float4*)&As[kk][ty * TM + 4];
            *(float4*)&b[0] = *(const float4*)&Bs[kk][tx * TN];
            *(float4*)&b[4] = *(const float4*)&Bs[kk][tx * TN + 4];
#pragma unroll
            for (int i = 0; i < TM; ++i)
#pragma unroll
                for (int j = 0; j < TN; ++j)
                    acc[i][j] = fmaf(a[i], b[j], acc[i][j]);
        }
        __syncthreads();
    }

    float* Cb = C + (size_t)(blockIdx.y * BM + ty * TM) * N + blockIdx.x * BN + tx * TN;
#pragma unroll
    for (int i = 0; i < TM; ++i) {
        *(float4*)(Cb + (size_t)i * N)     = make_float4(acc[i][0], acc[i][1], acc[i][2], acc[i][3]);
        *(float4*)(Cb + (size_t)i * N + 4) = make_float4(acc[i][4], acc[i][5], acc[i][6], acc[i][7]);
    }
}

// ---------------------------------------------------------------------------
// Scores: S[b,q,k] = (Q[b,q,:] . K[b,k,:]) * inv_scale, lower triangle only.
// Tiles strictly above the diagonal are skipped (softmax never reads k > q).
// ---------------------------------------------------------------------------
__global__ __launch_bounds__(NTHREADS, 2)
void scores_kernel(const float* __restrict__ Q, const float* __restrict__ Km,
                   float* __restrict__ S, float inv_scale)
{
    if (blockIdx.x > blockIdx.y) return;  // fully-masked tile

    __shared__ float As[BK][BM + PAD];
    __shared__ float Bs[BK][BN + PAD];

    const int tid = threadIdx.x;
    const int tx = tid & 15;
    const int ty = tid >> 4;
    const int bz = blockIdx.z;

    const float* Ab = Q  + (size_t)bz * SEQ * DIM + (size_t)blockIdx.y * BM * DIM;
    const float* Bb = Km + (size_t)bz * SEQ * DIM + (size_t)blockIdx.x * BN * DIM;

    const int lrow = tid >> 1;
    const int lk4  = (tid & 1) * 4;

    float acc[TM][TN] = {};

    for (int k0 = 0; k0 < DIM; k0 += BK) {
        float4 av = *(const float4*)(Ab + (size_t)lrow * DIM + k0 + lk4);
        float4 bv = *(const float4*)(Bb + (size_t)lrow * DIM + k0 + lk4);
        As[lk4 + 0][lrow] = av.x; As[lk4 + 1][lrow] = av.y;
        As[lk4 + 2][lrow] = av.z; As[lk4 + 3][lrow] = av.w;
        Bs[lk4 + 0][lrow] = bv.x; Bs[lk4 + 1][lrow] = bv.y;
        Bs[lk4 + 2][lrow] = bv.z; Bs[lk4 + 3][lrow] = bv.w;
        __syncthreads();

#pragma unroll
        for (int kk = 0; kk < BK; ++kk) {
            float a[TM], b[TN];
            *(float4*)&a[0] = *(const float4*)&As[kk][ty * TM];
            *(float4*)&a[4] = *(const float4*)&As[kk][ty * TM + 4];
            *(float4*)&b[0] = *(const float4*)&Bs[kk][tx * TN];
            *(float4*)&b[4] = *(const float4*)&Bs[kk][tx * TN + 4];
#pragma unroll
            for (int i = 0; i < TM; ++i)
#pragma unroll
                for (int j = 0; j < TN; ++j)
                    acc[i][j] = fmaf(a[i], b[j], acc[i][j]);
        }
        __syncthreads();
    }

    float* Cb = S + (size_t)bz * SEQ * SEQ
                  + (size_t)(blockIdx.y * BM + ty * TM) * SEQ + blockIdx.x * BN + tx * TN;
#pragma unroll
    for (int i = 0; i < TM; ++i) {
        *(float4*)(Cb + (size_t)i * SEQ) =
            make_float4(acc[i][0] * inv_scale, acc[i][1] * inv_scale,
                        acc[i][2] * inv_scale, acc[i][3] * inv_scale);
        *(float4*)(Cb + (size_t)i * SEQ + 4) =
            make_float4(acc[i][4] * inv_scale, acc[i][5] * inv_scale,
                        acc[i][6] * inv_scale, acc[i][7] * inv_scale);
    }
}

// ---------------------------------------------------------------------------
// Causal softmax, in place, one block per (b,q) row.
// Reads only k <= q (entries beyond are uninitialized garbage), writes full
// row: attn[k<=q] = exp(s-m)/sum, attn[k>q] = 0.
// ---------------------------------------------------------------------------
__global__ void softmax_kernel(float* __restrict__ S)
{
    const int row = blockIdx.x;           // 0 .. B*SEQ-1
    const int b = row / SEQ;
    const int q = row % SEQ;
    float* sr = S + ((size_t)b * SEQ + q) * SEQ;
    const int len = q + 1;

    __shared__ float sh[8];

    float m = -1e30f;
    for (int k = threadIdx.x; k < len; k += blockDim.x)
        m = fmaxf(m, sr[k]);
#pragma unroll
    for (int o = 16; o; o >>= 1)
        m = fmaxf(m, __shfl_xor_sync(0xffffffffu, m, o));
    if ((threadIdx.x & 31) == 0) sh[threadIdx.x >> 5] = m;
    __syncthreads();
    m = sh[0];
#pragma unroll
    for (int w = 1; w < 8; ++w) m = fmaxf(m, sh[w]);

    float sum = 0.f;
    for (int k = threadIdx.x; k < len; k += blockDim.x)
        sum += __expf(sr[k] - m);
#pragma unroll
    for (int o = 16; o; o >>= 1)
        sum += __shfl_xor_sync(0xffffffffu, sum, o);
    __syncthreads();   // protect sh reuse
    if ((threadIdx.x & 31) == 0) sh[threadIdx.x >> 5] = sum;
    __syncthreads();
    sum = 0.f;
#pragma unroll
    for (int w = 0; w < 8; ++w) sum += sh[w];

    const float inv = 1.0f / sum;
    for (int k = threadIdx.x; k < SEQ; k += blockDim.x)
        sr[k] = (k < len) ? __expf(sr[k] - m) * inv : 0.f;
}

// ---------------------------------------------------------------------------
// NN GEMM: Out[b] = Attn[b] (S x S, K-contig) * V[b] (S x D, N-contig).
// Causality bounds the K loop: rows in tile by touch only k < (by+1)*BM.
// ---------------------------------------------------------------------------
__global__ __launch_bounds__(NTHREADS, 2)
void av_kernel(const float* __restrict__ Attn, const float* __restrict__ V,
               float* __restrict__ Out)
{
    __shared__ float As[BK][BM + PAD];
    __shared__ float Bs[BK][BN + PAD];

    const int tid = threadIdx.x;
    const int tx = tid & 15;
    const int ty = tid >> 4;
    const int bz = blockIdx.z;

    const float* Ab = Attn + (size_t)bz * SEQ * SEQ + (size_t)blockIdx.y * BM * SEQ;
    const float* Vb = V + (size_t)bz * SEQ * DIM + blockIdx.x * BN;

    const int lrow = tid >> 1;        // A loader (K-contig, transpose into smem)
    const int lk4  = (tid & 1) * 4;
    const int brow = tid >> 5;        // B loader (N-contig, direct)
    const int bn4  = (tid & 31) * 4;

    float acc[TM][TN] = {};
    const int Klim = (blockIdx.y + 1) * BM;   // causal bound, multiple of BK

    for (int k0 = 0; k0 < Klim; k0 += BK) {
        float4 av = *(const float4*)(Ab + (size_t)lrow * SEQ + k0 + lk4);
        As[lk4 + 0][lrow] = av.x; As[lk4 + 1][lrow] = av.y;
        As[lk4 + 2][lrow] = av.z; As[lk4 + 3][lrow] = av.w;
        float4 bv = *(const float4*)(Vb + (size_t)(k0 + brow) * DIM + bn4);
        *(float4*)&Bs[brow][bn4] = bv;
        __syncthreads();

#pragma unroll
        for (int kk = 0; kk < BK; ++kk) {
            float a[TM], b[TN];
            *(float4*)&a[0] = *(const float4*)&As[kk][ty * TM];
            *(float4*)&a[4] = *(const float4*)&As[kk][ty * TM + 4];
            *(float4*)&b[0] = *(const float4*)&Bs[kk][tx * TN];
            *(float4*)&b[4] = *(const float4*)&Bs[kk][tx * TN + 4];
#pragma unroll
            for (int i = 0; i < TM; ++i)
#pragma unroll
                for (int j = 0; j < TN; ++j)
                    acc[i][j] = fmaf(a[i], b[j], acc[i][j]);
        }
        __syncthreads();
    }

    float* Cb = Out + (size_t)bz * SEQ * DIM
                    + (size_t)(blockIdx.y * BM + ty * TM) * DIM + blockIdx.x * BN + tx * TN;
#pragma unroll
    for (int i = 0; i < TM; ++i) {
        *(float4*)(Cb + (size_t)i * DIM)     = make_float4(acc[i][0], acc[i][1], acc[i][2], acc[i][3]);
        *(float4*)(Cb + (size_t)i * DIM + 4) = make_float4(acc[i][4], acc[i][5], acc[i][6], acc[i][7]);
    }
}

// ---------------------------------------------------------------------------
extern "C" void kernel_launch(void* const* d_in, const int* in_sizes, int n_in,
                              void* d_out, int out_size)
{
    const float* x  = (const float*)d_in[0];
    const float* Wk = (const float*)d_in[1];
    const float* Wq = (const float*)d_in[2];
    const float* Wv = (const float*)d_in[3];
    float* out = (float*)d_out;

    float *q, *k, *v, *s;
    cudaGetSymbolAddress((void**)&q, g_Q);
    cudaGetSymbolAddress((void**)&k, g_K);
    cudaGetSymbolAddress((void**)&v, g_V);
    cudaGetSymbolAddress((void**)&s, g_S);

    const float inv_scale = 1.0f / sqrtf((float)DIM);

    dim3 blk(NTHREADS);
    dim3 gproj(DIM / BN, (BATCH * SEQ) / BM);          // 16 x 64
    gemm_tn_kernel<<<gproj, blk>>>(x, Wq, q, DIM, EMB);
    gemm_tn_kernel<<<gproj, blk>>>(x, Wk, k, DIM, EMB);
    gemm_tn_kernel<<<gproj, blk>>>(x, Wv, v, DIM, EMB);

    dim3 gattn(SEQ / BN, SEQ / BM, BATCH);             // 16 x 16 x 4
    scores_kernel<<<gattn, blk>>>(q, k, s, inv_scale);

    softmax_kernel<<<BATCH * SEQ, 256>>>(s);

    av_kernel<<<gattn, blk>>>(s, v, out);
}

// round 7
// speedup vs baseline: 2.4029x; 2.4029x over previous
#include <cuda_runtime.h>
#include <cuda_bf16.h>
#include <math.h>
#include <stdint.h>

#define SEQ   2048
#define EMB   2048
#define DIM   2048
#define BATCH 4

typedef __nv_bfloat16 bf16;

// ---------------------------------------------------------------------------
// Device scratch (no cudaMalloc allowed anywhere)
// ---------------------------------------------------------------------------
__device__ bf16 g_xhi[(size_t)BATCH * SEQ * EMB];
__device__ bf16 g_xlo[(size_t)BATCH * SEQ * EMB];
__device__ bf16 g_Wqhi[(size_t)DIM * EMB];
__device__ bf16 g_Wqlo[(size_t)DIM * EMB];
__device__ bf16 g_Wkhi[(size_t)DIM * EMB];
__device__ bf16 g_Wklo[(size_t)DIM * EMB];
__device__ bf16 g_Wvhi[(size_t)DIM * EMB];
__device__ bf16 g_Wvlo[(size_t)DIM * EMB];
__device__ bf16 g_Qhi[(size_t)BATCH * SEQ * DIM];
__device__ bf16 g_Qlo[(size_t)BATCH * SEQ * DIM];
__device__ bf16 g_Khi[(size_t)BATCH * SEQ * DIM];
__device__ bf16 g_Klo[(size_t)BATCH * SEQ * DIM];
__device__ bf16 g_Vthi[(size_t)BATCH * DIM * SEQ];   // V^T per batch
__device__ bf16 g_Vtlo[(size_t)BATCH * DIM * SEQ];
__device__ float g_S [(size_t)BATCH * SEQ * SEQ];
__device__ bf16 g_Phi[(size_t)BATCH * SEQ * SEQ];
__device__ bf16 g_Plo[(size_t)BATCH * SEQ * SEQ];

// ---------------------------------------------------------------------------
// PTX helpers (sm_80-level PTX only; no arch-suffixed instructions)
// ---------------------------------------------------------------------------
__device__ __forceinline__ uint32_t smem_u32(const void* p) {
    uint32_t a;
    asm("{ .reg .u64 t; cvta.to.shared.u64 t, %1; cvt.u32.u64 %0, t; }"
        : "=r"(a) : "l"(p));
    return a;
}

__device__ __forceinline__ void cp16(uint32_t dst, const void* src) {
    asm volatile("cp.async.cg.shared.global [%0], [%1], 16;" :: "r"(dst), "l"(src));
}
__device__ __forceinline__ void cp_commit() {
    asm volatile("cp.async.commit_group;" ::: "memory");
}
template<int N> __device__ __forceinline__ void cp_wait() {
    asm volatile("cp.async.wait_group %0;" :: "n"(N) : "memory");
}

__device__ __forceinline__ void ldm4(uint32_t& r0, uint32_t& r1, uint32_t& r2,
                                     uint32_t& r3, uint32_t addr) {
    asm volatile("ldmatrix.sync.aligned.m8n8.x4.shared.b16 {%0,%1,%2,%3}, [%4];"
                 : "=r"(r0), "=r"(r1), "=r"(r2), "=r"(r3) : "r"(addr));
}

__device__ __forceinline__ void mma16816(float* c, const uint32_t* a,
                                         uint32_t b0, uint32_t b1) {
    asm volatile(
        "mma.sync.aligned.m16n8k16.row.col.f32.bf16.bf16.f32 "
        "{%0,%1,%2,%3}, {%4,%5,%6,%7}, {%8,%9}, {%0,%1,%2,%3};"
        : "+f"(c[0]), "+f"(c[1]), "+f"(c[2]), "+f"(c[3])
        : "r"(a[0]), "r"(a[1]), "r"(a[2]), "r"(a[3]), "r"(b0), "r"(b1));
}

// ---------------------------------------------------------------------------
// Tiling constants
// ---------------------------------------------------------------------------
#define ROWB 80                     // smem row stride bytes (32 bf16 = 64B data + 16B pad)
#define TILEB (128 * ROWB)          // 10240 B per 128x32 tile
#define STAGEB (4 * TILEB)          // Ah, Al, Bh, Bl
static constexpr unsigned SMEM_BYTES = 2 * STAGEB;   // 81920 (also covers 2x34816 transpose stage)

// ---------------------------------------------------------------------------
// Templated HMMA GEMM: C[128x128] = Ah@Bh^T + Ah@Bl^T + Al@Bh^T
// Operands K-major (leading dim 2048).
//   MODE 0: projection -> out hi/lo bf16 row-major [8192, 2048]
//   MODE 1: projection -> out hi/lo bf16 transposed per batch (V^T), smem-staged
//   MODE 2: scores     -> out fp32 * scale, per batch, causal tile skip
//   MODE 3: attn @ V^T -> out fp32 per batch, causal K bound
// ---------------------------------------------------------------------------
template<int MODE>
__global__ __launch_bounds__(256)
void mma_gemm(const bf16* __restrict__ Ahi, const bf16* __restrict__ Alo,
              const bf16* __restrict__ Bhi, const bf16* __restrict__ Blo,
              float* __restrict__ out_f,
              bf16* __restrict__ out_hi, bf16* __restrict__ out_lo,
              float scale)
{
    const int bx = blockIdx.x, by = blockIdx.y, bz = blockIdx.z;
    if (MODE == 2 && bx > by) return;     // fully masked score tile

    extern __shared__ char smem[];
    const uint32_t sbase = smem_u32(smem);

    const int tid    = threadIdx.x;
    const int wid    = tid >> 5;
    const int lane   = tid & 31;
    const int warp_m = wid & 3;           // 4 x 32 rows
    const int warp_n = wid >> 2;          // 2 x 64 cols

    const size_t boff_mat = (MODE >= 2) ? (size_t)bz * 2048 * 2048 : 0;

    const bf16* Ah = Ahi + boff_mat + (size_t)(by * 128) * 2048;
    const bf16* Al = Alo + boff_mat + (size_t)(by * 128) * 2048;
    const bf16* Bh = Bhi + boff_mat + (size_t)(bx * 128) * 2048;
    const bf16* Bl = Blo + boff_mat + (size_t)(bx * 128) * 2048;

    const int nk = (MODE == 3) ? (by + 1) * 4 : 64;   // number of 32-wide K chunks

    // loader: thread t covers rows (t>>2) and (t>>2)+64, 16B chunk (t&3)
    const int lrow = tid >> 2;
    const int lcb  = (tid & 3) * 16;

    auto load_stage = [&](int kc) {
        const uint32_t sd = sbase + (kc & 1) * STAGEB;
        const size_t goff = (size_t)kc * 32;           // element offset in K
        const char* pa0 = (const char*)(Ah + goff);
        const char* pa1 = (const char*)(Al + goff);
        const char* pb0 = (const char*)(Bh + goff);
        const char* pb1 = (const char*)(Bl + goff);
#pragma unroll
        for (int i = 0; i < 2; ++i) {
            const int r = lrow + i * 64;
            const uint32_t so = (uint32_t)r * ROWB + lcb;
            const size_t go = (size_t)r * 4096 + lcb;  // 2048 elems * 2B
            cp16(sd + 0 * TILEB + so, pa0 + go);
            cp16(sd + 1 * TILEB + so, pa1 + go);
            cp16(sd + 2 * TILEB + so, pb0 + go);
            cp16(sd + 3 * TILEB + so, pb1 + go);
        }
        cp_commit();
    };

    float acc[2][8][4] = {};

    load_stage(0);

    for (int s = 0; s < nk; ++s) {
        if (s + 1 < nk) { load_stage(s + 1); cp_wait<1>(); }
        else            { cp_wait<0>(); }
        __syncthreads();

        const uint32_t sd = sbase + (s & 1) * STAGEB;
        const uint32_t lrh = (uint32_t)(lane & 15) * ROWB + (uint32_t)(lane >> 4) * 16;

        // ---- two k16 halves per 32-wide chunk (THE round-3 bug fix) ----
#pragma unroll
        for (int half = 0; half < 2; ++half) {
            const uint32_t hb = lrh + (uint32_t)half * 32;   // byte offset of k-half

            uint32_t ah[2][4], al2[2][4], bh[4][4], bl[4][4];
#pragma unroll
            for (int mt = 0; mt < 2; ++mt) {
                const uint32_t ro = (uint32_t)(warp_m * 32 + mt * 16) * ROWB + hb;
                ldm4(ah[mt][0],  ah[mt][1],  ah[mt][2],  ah[mt][3],  sd + 0 * TILEB + ro);
                ldm4(al2[mt][0], al2[mt][1], al2[mt][2], al2[mt][3], sd + 1 * TILEB + ro);
            }
#pragma unroll
            for (int g = 0; g < 4; ++g) {
                const uint32_t ro = (uint32_t)(warp_n * 64 + g * 16) * ROWB + hb;
                ldm4(bh[g][0], bh[g][1], bh[g][2], bh[g][3], sd + 2 * TILEB + ro);
                ldm4(bl[g][0], bl[g][1], bl[g][2], bl[g][3], sd + 3 * TILEB + ro);
            }

            // ---- 3 product passes ----
#pragma unroll
            for (int mt = 0; mt < 2; ++mt)
#pragma unroll
                for (int nt = 0; nt < 8; ++nt) {
                    const int g = nt >> 1, o = nt & 1;
                    mma16816(acc[mt][nt], ah[mt],  bh[g][o], bh[g][2 + o]);
                    mma16816(acc[mt][nt], ah[mt],  bl[g][o], bl[g][2 + o]);
                    mma16816(acc[mt][nt], al2[mt], bh[g][o], bh[g][2 + o]);
                }
        }
        __syncthreads();
    }

    // ---- epilogue ----
    const int tq = lane >> 2;      // row within 8
    const int tr = lane & 3;       // col pair

    if (MODE == 1) {
        // stage hi/lo tiles in smem, then coalesced transposed write
#pragma unroll
        for (int mt = 0; mt < 2; ++mt)
#pragma unroll
            for (int nt = 0; nt < 8; ++nt) {
                const int ml = warp_m * 32 + mt * 16 + tq;
                const int nl = warp_n * 64 + nt * 8 + tr * 2;
#pragma unroll
                for (int h = 0; h < 2; ++h) {
                    const float c0 = acc[mt][nt][h * 2 + 0];
                    const float c1 = acc[mt][nt][h * 2 + 1];
                    const bf16 h0 = __float2bfloat16(c0);
                    const bf16 h1 = __float2bfloat16(c1);
                    const bf16 l0 = __float2bfloat16(c0 - __bfloat162float(h0));
                    const bf16 l1 = __float2bfloat16(c1 - __bfloat162float(h1));
                    const uint32_t so = (uint32_t)(ml + h * 8) * 272 + (uint32_t)nl * 2;
                    *(__nv_bfloat162*)(smem + so)         = __halves2bfloat162(h0, h1);
                    *(__nv_bfloat162*)(smem + 34816 + so) = __halves2bfloat162(l0, l1);
                }
            }
        __syncthreads();
        // write out: token rows of this tile are one contiguous st-range of one batch
        const int b   = by >> 4;
        const int st0 = (by & 15) * 128;
        const int nl  = tid >> 1;          // 0..127 (output row = dim index)
        const int hh  = tid & 1;           // which 64-token half
        const size_t obase = ((size_t)b * 2048 + bx * 128 + nl) * 2048 + st0 + hh * 64;
#pragma unroll 4
        for (int j = 0; j < 64; j += 2) {
            const uint32_t s0 = (uint32_t)(hh * 64 + j) * 272 + (uint32_t)nl * 2;
            bf16 a0 = *(const bf16*)(smem + s0);
            bf16 a1 = *(const bf16*)(smem + s0 + 272);
            *(__nv_bfloat162*)(out_hi + obase + j) = __halves2bfloat162(a0, a1);
            bf16 c0 = *(const bf16*)(smem + 34816 + s0);
            bf16 c1 = *(const bf16*)(smem + 34816 + s0 + 272);
            *(__nv_bfloat162*)(out_lo + obase + j) = __halves2bfloat162(c0, c1);
        }
        return;
    }

#pragma unroll
    for (int mt = 0; mt < 2; ++mt)
#pragma unroll
        for (int nt = 0; nt < 8; ++nt) {
            const int gm = by * 128 + warp_m * 32 + mt * 16 + tq;
            const int gn = bx * 128 + warp_n * 64 + nt * 8 + tr * 2;
#pragma unroll
            for (int h = 0; h < 2; ++h) {
                const float c0 = acc[mt][nt][h * 2 + 0];
                const float c1 = acc[mt][nt][h * 2 + 1];
                if (MODE == 0) {
                    const size_t o = (size_t)(gm + h * 8) * 2048 + gn;
                    const bf16 h0 = __float2bfloat16(c0);
                    const bf16 h1 = __float2bfloat16(c1);
                    *(__nv_bfloat162*)(out_hi + o) = __halves2bfloat162(h0, h1);
                    *(__nv_bfloat162*)(out_lo + o) = __halves2bfloat162(
                        __float2bfloat16(c0 - __bfloat162float(h0)),
                        __float2bfloat16(c1 - __bfloat162float(h1)));
                } else {
                    const float sc = (MODE == 2) ? scale : 1.0f;
                    const size_t o = (size_t)bz * 2048 * 2048 + (size_t)(gm + h * 8) * 2048 + gn;
                    *(float2*)(out_f + o) = make_float2(c0 * sc, c1 * sc);
                }
            }
        }
}

// ---------------------------------------------------------------------------
// fp32 -> (bf16 hi, bf16 lo) split
// ---------------------------------------------------------------------------
__global__ void split_kernel(const float* __restrict__ s,
                             bf16* __restrict__ hi, bf16* __restrict__ lo, int n)
{
    int i = blockIdx.x * blockDim.x + threadIdx.x;
    if (i < n) {
        float v = s[i];
        bf16 h = __float2bfloat16(v);
        hi[i] = h;
        lo[i] = __float2bfloat16(v - __bfloat162float(h));
    }
}

// ---------------------------------------------------------------------------
// Causal softmax: fp32 scores (k<=q valid) -> attn hi/lo bf16, zero above diag
// ---------------------------------------------------------------------------
__global__ void softmax_kernel(const float* __restrict__ S,
                               bf16* __restrict__ Phi, bf16* __restrict__ Plo)
{
    const int row = blockIdx.x;
    const int b = row / SEQ;
    const int q = row % SEQ;
    const float* sr = S + ((size_t)b * SEQ + q) * SEQ;
    const size_t ob = ((size_t)b * SEQ + q) * SEQ;
    const int len = q + 1;

    __shared__ float sh[8];

    float m = -1e30f;
    for (int k = threadIdx.x; k < len; k += blockDim.x)
        m = fmaxf(m, sr[k]);
#pragma unroll
    for (int o = 16; o; o >>= 1)
        m = fmaxf(m, __shfl_xor_sync(0xffffffffu, m, o));
    if ((threadIdx.x & 31) == 0) sh[threadIdx.x >> 5] = m;
    __syncthreads();
    m = sh[0];
#pragma unroll
    for (int w = 1; w < 8; ++w) m = fmaxf(m, sh[w]);

    float sum = 0.f;
    for (int k = threadIdx.x; k < len; k += blockDim.x)
        sum += __expf(sr[k] - m);
#pragma unroll
    for (int o = 16; o; o >>= 1)
        sum += __shfl_xor_sync(0xffffffffu, sum, o);
    __syncthreads();
    if ((threadIdx.x & 31) == 0) sh[threadIdx.x >> 5] = sum;
    __syncthreads();
    sum = 0.f;
#pragma unroll
    for (int w = 0; w < 8; ++w) sum += sh[w];

    const float inv = 1.0f / sum;
    for (int k = threadIdx.x; k < SEQ; k += blockDim.x) {
        if (k < len) {
            float a = __expf(sr[k] - m) * inv;
            bf16 h = __float2bfloat16(a);
            Phi[ob + k] = h;
            Plo[ob + k] = __float2bfloat16(a - __bfloat162float(h));
        } else {
            Phi[ob + k] = __float2bfloat16(0.f);
            Plo[ob + k] = __float2bfloat16(0.f);
        }
    }
}

// ---------------------------------------------------------------------------
extern "C" void kernel_launch(void* const* d_in, const int* in_sizes, int n_in,
                              void* d_out, int out_size)
{
    const float* x  = (const float*)d_in[0];
    const float* Wk = (const float*)d_in[1];
    const float* Wq = (const float*)d_in[2];
    const float* Wv = (const float*)d_in[3];
    float* out = (float*)d_out;

    bf16 *xhi, *xlo, *wqh, *wql, *wkh, *wkl, *wvh, *wvl;
    bf16 *qhi, *qlo, *khi, *klo, *vthi, *vtlo, *phi, *plo;
    float* s;
    cudaGetSymbolAddress((void**)&xhi,  g_xhi);
    cudaGetSymbolAddress((void**)&xlo,  g_xlo);
    cudaGetSymbolAddress((void**)&wqh,  g_Wqhi);
    cudaGetSymbolAddress((void**)&wql,  g_Wqlo);
    cudaGetSymbolAddress((void**)&wkh,  g_Wkhi);
    cudaGetSymbolAddress((void**)&wkl,  g_Wklo);
    cudaGetSymbolAddress((void**)&wvh,  g_Wvhi);
    cudaGetSymbolAddress((void**)&wvl,  g_Wvlo);
    cudaGetSymbolAddress((void**)&qhi,  g_Qhi);
    cudaGetSymbolAddress((void**)&qlo,  g_Qlo);
    cudaGetSymbolAddress((void**)&khi,  g_Khi);
    cudaGetSymbolAddress((void**)&klo,  g_Klo);
    cudaGetSymbolAddress((void**)&vthi, g_Vthi);
    cudaGetSymbolAddress((void**)&vtlo, g_Vtlo);
    cudaGetSymbolAddress((void**)&phi,  g_Phi);
    cudaGetSymbolAddress((void**)&plo,  g_Plo);
    cudaGetSymbolAddress((void**)&s,    g_S);

    cudaFuncSetAttribute(mma_gemm<0>, cudaFuncAttributeMaxDynamicSharedMemorySize, SMEM_BYTES);
    cudaFuncSetAttribute(mma_gemm<1>, cudaFuncAttributeMaxDynamicSharedMemorySize, SMEM_BYTES);
    cudaFuncSetAttribute(mma_gemm<2>, cudaFuncAttributeMaxDynamicSharedMemorySize, SMEM_BYTES);
    cudaFuncSetAttribute(mma_gemm<3>, cudaFuncAttributeMaxDynamicSharedMemorySize, SMEM_BYTES);

    const float inv_scale = 1.0f / sqrtf((float)DIM);

    {
        int n = BATCH * SEQ * EMB;
        split_kernel<<<(n + 255) / 256, 256>>>(x, xhi, xlo, n);
        int nw = DIM * EMB;
        split_kernel<<<(nw + 255) / 256, 256>>>(Wq, wqh, wql, nw);
        split_kernel<<<(nw + 255) / 256, 256>>>(Wk, wkh, wkl, nw);
        split_kernel<<<(nw + 255) / 256, 256>>>(Wv, wvh, wvl, nw);
    }

    dim3 blk(256);
    dim3 gproj(DIM / 128, (BATCH * SEQ) / 128);         // 16 x 64
    mma_gemm<0><<<gproj, blk, SMEM_BYTES>>>(xhi, xlo, wqh, wql, nullptr, qhi, qlo, 0.f);
    mma_gemm<0><<<gproj, blk, SMEM_BYTES>>>(xhi, xlo, wkh, wkl, nullptr, khi, klo, 0.f);
    mma_gemm<1><<<gproj, blk, SMEM_BYTES>>>(xhi, xlo, wvh, wvl, nullptr, vthi, vtlo, 0.f);

    dim3 gattn(SEQ / 128, SEQ / 128, BATCH);            // 16 x 16 x 4
    mma_gemm<2><<<gattn, blk, SMEM_BYTES>>>(qhi, qlo, khi, klo, s, nullptr, nullptr, inv_scale);

    softmax_kernel<<<BATCH * SEQ, 256>>>(s, phi, plo);

    mma_gemm<3><<<gattn, blk, SMEM_BYTES>>>(phi, plo, vthi, vtlo, out, nullptr, nullptr, 0.f);
}

// round 8
// speedup vs baseline: 2.9780x; 1.2393x over previous
#include <cuda_runtime.h>
#include <cuda_fp16.h>
#include <math.h>
#include <stdint.h>

#define SEQ   2048
#define EMB   2048
#define DIM   2048
#define BATCH 4

typedef __half h16;

// ---------------------------------------------------------------------------
// Device scratch (no cudaMalloc allowed anywhere)
// ---------------------------------------------------------------------------
__device__ h16 g_xhi[(size_t)BATCH * SEQ * EMB];
__device__ h16 g_xlo[(size_t)BATCH * SEQ * EMB];
__device__ h16 g_Wqhi[(size_t)DIM * EMB];
__device__ h16 g_Wkhi[(size_t)DIM * EMB];
__device__ h16 g_Wvhi[(size_t)DIM * EMB];
__device__ h16 g_Qhi[(size_t)BATCH * SEQ * DIM];
__device__ h16 g_Qlo[(size_t)BATCH * SEQ * DIM];
__device__ h16 g_Khi[(size_t)BATCH * SEQ * DIM];
__device__ h16 g_Klo[(size_t)BATCH * SEQ * DIM];
__device__ h16 g_Vthi[(size_t)BATCH * DIM * SEQ];   // V^T per batch
__device__ h16 g_Vtlo[(size_t)BATCH * DIM * SEQ];
__device__ float g_S [(size_t)BATCH * SEQ * SEQ];
__device__ h16 g_Phi[(size_t)BATCH * SEQ * SEQ];
__device__ h16 g_Plo[(size_t)BATCH * SEQ * SEQ];

// ---------------------------------------------------------------------------
// PTX helpers (sm_80-level PTX only; no arch-suffixed instructions)
// ---------------------------------------------------------------------------
__device__ __forceinline__ uint32_t smem_u32(const void* p) {
    uint32_t a;
    asm("{ .reg .u64 t; cvta.to.shared.u64 t, %1; cvt.u32.u64 %0, t; }"
        : "=r"(a) : "l"(p));
    return a;
}

__device__ __forceinline__ void cp16(uint32_t dst, const void* src) {
    asm volatile("cp.async.cg.shared.global [%0], [%1], 16;" :: "r"(dst), "l"(src));
}
__device__ __forceinline__ void cp_commit() {
    asm volatile("cp.async.commit_group;" ::: "memory");
}
template<int N> __device__ __forceinline__ void cp_wait() {
    asm volatile("cp.async.wait_group %0;" :: "n"(N) : "memory");
}

__device__ __forceinline__ void ldm4(uint32_t& r0, uint32_t& r1, uint32_t& r2,
                                     uint32_t& r3, uint32_t addr) {
    asm volatile("ldmatrix.sync.aligned.m8n8.x4.shared.b16 {%0,%1,%2,%3}, [%4];"
                 : "=r"(r0), "=r"(r1), "=r"(r2), "=r"(r3) : "r"(addr));
}

__device__ __forceinline__ void mma16816(float* c, const uint32_t* a,
                                         uint32_t b0, uint32_t b1) {
    asm volatile(
        "mma.sync.aligned.m16n8k16.row.col.f32.f16.f16.f32 "
        "{%0,%1,%2,%3}, {%4,%5,%6,%7}, {%8,%9}, {%0,%1,%2,%3};"
        : "+f"(c[0]), "+f"(c[1]), "+f"(c[2]), "+f"(c[3])
        : "r"(a[0]), "r"(a[1]), "r"(a[2]), "r"(a[3]), "r"(b0), "r"(b1));
}

// ---------------------------------------------------------------------------
// Tiling constants
// ---------------------------------------------------------------------------
#define ROWB 80                     // smem row stride bytes (32 h16 = 64B data + 16B pad)
#define TILEB (128 * ROWB)          // 10240 B per 128x32 tile
static constexpr unsigned SMEM_BYTES = 81920;   // max over all modes (4-tile x2 stages)

// ---------------------------------------------------------------------------
// Templated HMMA GEMM, operands K-major (ld 2048), fp16 split-precision.
//   NPASS=2: C = Ah@Bh^T + Al@Bh^T   (tiles: Ah, Al, Bh)      -- projections
//   NPASS=3: C = Ah@Bh^T + Ah@Bl^T + Al@Bh^T (tiles: Ah,Al,Bh,Bl) -- attention
//   MODE 0: projection -> out hi/lo fp16 row-major [8192, 2048]
//   MODE 1: projection -> out hi/lo fp16 transposed per batch (V^T), smem-staged
//   MODE 2: scores     -> out fp32 * scale, per batch, causal tile skip
//   MODE 3: attn @ V^T -> out fp32 per batch, causal K bound
// ---------------------------------------------------------------------------
template<int MODE, int NPASS>
__global__ __launch_bounds__(256)
void mma_gemm(const h16* __restrict__ Ahi, const h16* __restrict__ Alo,
              const h16* __restrict__ Bhi, const h16* __restrict__ Blo,
              float* __restrict__ out_f,
              h16* __restrict__ out_hi, h16* __restrict__ out_lo,
              float scale)
{
    constexpr int NT = (NPASS == 2) ? 3 : 4;        // tiles per stage
    constexpr uint32_t STG = NT * TILEB;

    const int bx = blockIdx.x, by = blockIdx.y, bz = blockIdx.z;
    if (MODE == 2 && bx > by) return;     // fully masked score tile

    extern __shared__ char smem[];
    const uint32_t sbase = smem_u32(smem);

    const int tid    = threadIdx.x;
    const int wid    = tid >> 5;
    const int lane   = tid & 31;
    const int warp_m = wid & 3;           // 4 x 32 rows
    const int warp_n = wid >> 2;          // 2 x 64 cols

    const size_t boff_mat = (MODE >= 2) ? (size_t)bz * 2048 * 2048 : 0;

    const h16* Ah = Ahi + boff_mat + (size_t)(by * 128) * 2048;
    const h16* Al = Alo + boff_mat + (size_t)(by * 128) * 2048;
    const h16* Bh = Bhi + boff_mat + (size_t)(bx * 128) * 2048;
    const h16* Bl = (NPASS == 3) ? Blo + boff_mat + (size_t)(bx * 128) * 2048 : nullptr;

    const int nk = (MODE == 3) ? (by + 1) * 4 : 64;   // number of 32-wide K chunks

    // loader: thread t covers rows (t>>2) and (t>>2)+64, 16B chunk (t&3)
    const int lrow = tid >> 2;
    const int lcb  = (tid & 3) * 16;

    auto load_stage = [&](int kc) {
        const uint32_t sd = sbase + (kc & 1) * STG;
        const size_t goff = (size_t)kc * 32;           // element offset in K
        const char* pa0 = (const char*)(Ah + goff);
        const char* pa1 = (const char*)(Al + goff);
        const char* pb0 = (const char*)(Bh + goff);
        const char* pb1 = (NPASS == 3) ? (const char*)(Bl + goff) : nullptr;
#pragma unroll
        for (int i = 0; i < 2; ++i) {
            const int r = lrow + i * 64;
            const uint32_t so = (uint32_t)r * ROWB + lcb;
            const size_t go = (size_t)r * 4096 + lcb;  // 2048 elems * 2B
            cp16(sd + 0 * TILEB + so, pa0 + go);
            cp16(sd + 1 * TILEB + so, pa1 + go);
            cp16(sd + 2 * TILEB + so, pb0 + go);
            if (NPASS == 3) cp16(sd + 3 * TILEB + so, pb1 + go);
        }
        cp_commit();
    };

    float acc[2][8][4] = {};

    load_stage(0);

    for (int s = 0; s < nk; ++s) {
        if (s + 1 < nk) { load_stage(s + 1); cp_wait<1>(); }
        else            { cp_wait<0>(); }
        __syncthreads();

        const uint32_t sd = sbase + (s & 1) * STG;
        const uint32_t lrh = (uint32_t)(lane & 15) * ROWB + (uint32_t)(lane >> 4) * 16;

        // two k16 halves per 32-wide chunk
#pragma unroll
        for (int half = 0; half < 2; ++half) {
            const uint32_t hb = lrh + (uint32_t)half * 32;   // byte offset of k-half

            uint32_t ah[2][4], al2[2][4], bh[4][4], bl[4][4];
#pragma unroll
            for (int mt = 0; mt < 2; ++mt) {
                const uint32_t ro = (uint32_t)(warp_m * 32 + mt * 16) * ROWB + hb;
                ldm4(ah[mt][0],  ah[mt][1],  ah[mt][2],  ah[mt][3],  sd + 0 * TILEB + ro);
                ldm4(al2[mt][0], al2[mt][1], al2[mt][2], al2[mt][3], sd + 1 * TILEB + ro);
            }
#pragma unroll
            for (int g = 0; g < 4; ++g) {
                const uint32_t ro = (uint32_t)(warp_n * 64 + g * 16) * ROWB + hb;
                ldm4(bh[g][0], bh[g][1], bh[g][2], bh[g][3], sd + 2 * TILEB + ro);
                if (NPASS == 3)
                    ldm4(bl[g][0], bl[g][1], bl[g][2], bl[g][3], sd + 3 * TILEB + ro);
            }

#pragma unroll
            for (int mt = 0; mt < 2; ++mt)
#pragma unroll
                for (int nt = 0; nt < 8; ++nt) {
                    const int g = nt >> 1, o = nt & 1;
                    mma16816(acc[mt][nt], ah[mt],  bh[g][o], bh[g][2 + o]);
                    mma16816(acc[mt][nt], al2[mt], bh[g][o], bh[g][2 + o]);
                    if (NPASS == 3)
                        mma16816(acc[mt][nt], ah[mt], bl[g][o], bl[g][2 + o]);
                }
        }
        __syncthreads();
    }

    // ---- epilogue ----
    const int tq = lane >> 2;      // row within 8
    const int tr = lane & 3;       // col pair

    if (MODE == 1) {
        // stage hi/lo tiles in smem, then coalesced transposed write
#pragma unroll
        for (int mt = 0; mt < 2; ++mt)
#pragma unroll
            for (int nt = 0; nt < 8; ++nt) {
                const int ml = warp_m * 32 + mt * 16 + tq;
                const int nl = warp_n * 64 + nt * 8 + tr * 2;
#pragma unroll
                for (int h = 0; h < 2; ++h) {
                    const float c0 = acc[mt][nt][h * 2 + 0];
                    const float c1 = acc[mt][nt][h * 2 + 1];
                    const h16 h0 = __float2half_rn(c0);
                    const h16 h1 = __float2half_rn(c1);
                    const h16 l0 = __float2half_rn(c0 - __half2float(h0));
                    const h16 l1 = __float2half_rn(c1 - __half2float(h1));
                    const uint32_t so = (uint32_t)(ml + h * 8) * 272 + (uint32_t)nl * 2;
                    *(__half2*)(smem + so)         = __halves2half2(h0, h1);
                    *(__half2*)(smem + 34816 + so) = __halves2half2(l0, l1);
                }
            }
        __syncthreads();
        // write out: token rows of this tile are one contiguous st-range of one batch
        const int b   = by >> 4;
        const int st0 = (by & 15) * 128;
        const int nl  = tid >> 1;          // 0..127 (output row = dim index)
        const int hh  = tid & 1;           // which 64-token half
        const size_t obase = ((size_t)b * 2048 + bx * 128 + nl) * 2048 + st0 + hh * 64;
#pragma unroll 4
        for (int j = 0; j < 64; j += 2) {
            const uint32_t s0 = (uint32_t)(hh * 64 + j) * 272 + (uint32_t)nl * 2;
            h16 a0 = *(const h16*)(smem + s0);
            h16 a1 = *(const h16*)(smem + s0 + 272);
            *(__half2*)(out_hi + obase + j) = __halves2half2(a0, a1);
            h16 c0 = *(const h16*)(smem + 34816 + s0);
            h16 c1 = *(const h16*)(smem + 34816 + s0 + 272);
            *(__half2*)(out_lo + obase + j) = __halves2half2(c0, c1);
        }
        return;
    }

#pragma unroll
    for (int mt = 0; mt < 2; ++mt)
#pragma unroll
        for (int nt = 0; nt < 8; ++nt) {
            const int gm = by * 128 + warp_m * 32 + mt * 16 + tq;
            const int gn = bx * 128 + warp_n * 64 + nt * 8 + tr * 2;
#pragma unroll
            for (int h = 0; h < 2; ++h) {
                const float c0 = acc[mt][nt][h * 2 + 0];
                const float c1 = acc[mt][nt][h * 2 + 1];
                if (MODE == 0) {
                    const size_t o = (size_t)(gm + h * 8) * 2048 + gn;
                    const h16 h0 = __float2half_rn(c0);
                    const h16 h1 = __float2half_rn(c1);
                    *(__half2*)(out_hi + o) = __halves2half2(h0, h1);
                    *(__half2*)(out_lo + o) = __halves2half2(
                        __float2half_rn(c0 - __half2float(h0)),
                        __float2half_rn(c1 - __half2float(h1)));
                } else {
                    const float sc = (MODE == 2) ? scale : 1.0f;
                    const size_t o = (size_t)bz * 2048 * 2048 + (size_t)(gm + h * 8) * 2048 + gn;
                    *(float2*)(out_f + o) = make_float2(c0 * sc, c1 * sc);
                }
            }
        }
}

// ---------------------------------------------------------------------------
// fp32 -> (fp16 hi, fp16 lo) split, and hi-only variant (for weights)
// ---------------------------------------------------------------------------
__global__ void split_kernel(const float* __restrict__ s,
                             h16* __restrict__ hi, h16* __restrict__ lo, int n)
{
    int i = blockIdx.x * blockDim.x + threadIdx.x;
    if (i < n) {
        float v = s[i];
        h16 h = __float2half_rn(v);
        hi[i] = h;
        lo[i] = __float2half_rn(v - __half2float(h));
    }
}

__global__ void split_hi_kernel(const float* __restrict__ s,
                                h16* __restrict__ hi, int n)
{
    int i = blockIdx.x * blockDim.x + threadIdx.x;
    if (i < n) hi[i] = __float2half_rn(s[i]);
}

// ---------------------------------------------------------------------------
// Causal softmax: fp32 scores (k<=q valid) -> attn hi/lo fp16, zero above diag
// ---------------------------------------------------------------------------
__global__ void softmax_kernel(const float* __restrict__ S,
                               h16* __restrict__ Phi, h16* __restrict__ Plo)
{
    const int row = blockIdx.x;
    const int b = row / SEQ;
    const int q = row % SEQ;
    const float* sr = S + ((size_t)b * SEQ + q) * SEQ;
    const size_t ob = ((size_t)b * SEQ + q) * SEQ;
    const int len = q + 1;

    __shared__ float sh[8];

    float m = -1e30f;
    for (int k = threadIdx.x; k < len; k += blockDim.x)
        m = fmaxf(m, sr[k]);
#pragma unroll
    for (int o = 16; o; o >>= 1)
        m = fmaxf(m, __shfl_xor_sync(0xffffffffu, m, o));
    if ((threadIdx.x & 31) == 0) sh[threadIdx.x >> 5] = m;
    __syncthreads();
    m = sh[0];
#pragma unroll
    for (int w = 1; w < 8; ++w) m = fmaxf(m, sh[w]);

    float sum = 0.f;
    for (int k = threadIdx.x; k < len; k += blockDim.x)
        sum += __expf(sr[k] - m);
#pragma unroll
    for (int o = 16; o; o >>= 1)
        sum += __shfl_xor_sync(0xffffffffu, sum, o);
    __syncthreads();
    if ((threadIdx.x & 31) == 0) sh[threadIdx.x >> 5] = sum;
    __syncthreads();
    sum = 0.f;
#pragma unroll
    for (int w = 0; w < 8; ++w) sum += sh[w];

    const float inv = 1.0f / sum;
    for (int k = threadIdx.x; k < SEQ; k += blockDim.x) {
        if (k < len) {
            float a = __expf(sr[k] - m) * inv;
            h16 h = __float2half_rn(a);
            Phi[ob + k] = h;
            Plo[ob + k] = __float2half_rn(a - __half2float(h));
        } else {
            Phi[ob + k] = __float2half_rn(0.f);
            Plo[ob + k] = __float2half_rn(0.f);
        }
    }
}

// ---------------------------------------------------------------------------
extern "C" void kernel_launch(void* const* d_in, const int* in_sizes, int n_in,
                              void* d_out, int out_size)
{
    const float* x  = (const float*)d_in[0];
    const float* Wk = (const float*)d_in[1];
    const float* Wq = (const float*)d_in[2];
    const float* Wv = (const float*)d_in[3];
    float* out = (float*)d_out;

    h16 *xhi, *xlo, *wqh, *wkh, *wvh;
    h16 *qhi, *qlo, *khi, *klo, *vthi, *vtlo, *phi, *plo;
    float* s;
    cudaGetSymbolAddress((void**)&xhi,  g_xhi);
    cudaGetSymbolAddress((void**)&xlo,  g_xlo);
    cudaGetSymbolAddress((void**)&wqh,  g_Wqhi);
    cudaGetSymbolAddress((void**)&wkh,  g_Wkhi);
    cudaGetSymbolAddress((void**)&wvh,  g_Wvhi);
    cudaGetSymbolAddress((void**)&qhi,  g_Qhi);
    cudaGetSymbolAddress((void**)&qlo,  g_Qlo);
    cudaGetSymbolAddress((void**)&khi,  g_Khi);
    cudaGetSymbolAddress((void**)&klo,  g_Klo);
    cudaGetSymbolAddress((void**)&vthi, g_Vthi);
    cudaGetSymbolAddress((void**)&vtlo, g_Vtlo);
    cudaGetSymbolAddress((void**)&phi,  g_Phi);
    cudaGetSymbolAddress((void**)&plo,  g_Plo);
    cudaGetSymbolAddress((void**)&s,    g_S);

    cudaFuncSetAttribute(mma_gemm<0,2>, cudaFuncAttributeMaxDynamicSharedMemorySize, SMEM_BYTES);
    cudaFuncSetAttribute(mma_gemm<1,2>, cudaFuncAttributeMaxDynamicSharedMemorySize, SMEM_BYTES);
    cudaFuncSetAttribute(mma_gemm<2,3>, cudaFuncAttributeMaxDynamicSharedMemorySize, SMEM_BYTES);
    cudaFuncSetAttribute(mma_gemm<3,3>, cudaFuncAttributeMaxDynamicSharedMemorySize, SMEM_BYTES);

    const float inv_scale = 1.0f / sqrtf((float)DIM);

    {
        int n = BATCH * SEQ * EMB;
        split_kernel<<<(n + 255) / 256, 256>>>(x, xhi, xlo, n);
        int nw = DIM * EMB;
        split_hi_kernel<<<(nw + 255) / 256, 256>>>(Wq, wqh, nw);
        split_hi_kernel<<<(nw + 255) / 256, 256>>>(Wk, wkh, nw);
        split_hi_kernel<<<(nw + 255) / 256, 256>>>(Wv, wvh, nw);
    }

    dim3 blk(256);
    dim3 gproj(DIM / 128, (BATCH * SEQ) / 128);         // 16 x 64
    mma_gemm<0,2><<<gproj, blk, SMEM_BYTES>>>(xhi, xlo, wqh, nullptr, nullptr, qhi, qlo, 0.f);
    mma_gemm<0,2><<<gproj, blk, SMEM_BYTES>>>(xhi, xlo, wkh, nullptr, nullptr, khi, klo, 0.f);
    mma_gemm<1,2><<<gproj, blk, SMEM_BYTES>>>(xhi, xlo, wvh, nullptr, nullptr, vthi, vtlo, 0.f);

    dim3 gattn(SEQ / 128, SEQ / 128, BATCH);            // 16 x 16 x 4
    mma_gemm<2,3><<<gattn, blk, SMEM_BYTES>>>(qhi, qlo, khi, klo, s, nullptr, nullptr, inv_scale);

    softmax_kernel<<<BATCH * SEQ, 256>>>(s, phi, plo);

    mma_gemm<3,3><<<gattn, blk, SMEM_BYTES>>>(phi, plo, vthi, vtlo, out, nullptr, nullptr, 0.f);
}

// round 10
// speedup vs baseline: 3.3974x; 1.1408x over previous
#include <cuda_runtime.h>
#include <cuda_fp16.h>
#include <math.h>
#include <stdint.h>

#define SEQ   2048
#define EMB   2048
#define DIM   2048
#define BATCH 4

typedef __half h16;

// ---------------------------------------------------------------------------
// Device scratch (no cudaMalloc allowed anywhere)
// ---------------------------------------------------------------------------
__device__ h16 g_xhi[(size_t)BATCH * SEQ * EMB];
__device__ h16 g_xlo[(size_t)BATCH * SEQ * EMB];
__device__ h16 g_Wqhi[(size_t)DIM * EMB];
__device__ h16 g_Wkhi[(size_t)DIM * EMB];
__device__ h16 g_Wvhi[(size_t)DIM * EMB];
__device__ h16 g_Qhi[(size_t)BATCH * SEQ * DIM];
__device__ h16 g_Qlo[(size_t)BATCH * SEQ * DIM];
__device__ h16 g_Khi[(size_t)BATCH * SEQ * DIM];
__device__ h16 g_Vthi[(size_t)BATCH * DIM * SEQ];   // V^T per batch, hi only
__device__ float g_S [(size_t)BATCH * SEQ * SEQ];
__device__ h16 g_Phi[(size_t)BATCH * SEQ * SEQ];
__device__ h16 g_Plo[(size_t)BATCH * SEQ * SEQ];

// ---------------------------------------------------------------------------
// PTX helpers (sm_80-level PTX only; no arch-suffixed instructions)
// ---------------------------------------------------------------------------
__device__ __forceinline__ uint32_t smem_u32(const void* p) {
    uint32_t a;
    asm("{ .reg .u64 t; cvta.to.shared.u64 t, %1; cvt.u32.u64 %0, t; }"
        : "=r"(a) : "l"(p));
    return a;
}

__device__ __forceinline__ void cp16(uint32_t dst, const void* src) {
    asm volatile("cp.async.cg.shared.global [%0], [%1], 16;" :: "r"(dst), "l"(src));
}
__device__ __forceinline__ void cp_commit() {
    asm volatile("cp.async.commit_group;" ::: "memory");
}
template<int N> __device__ __forceinline__ void cp_wait() {
    asm volatile("cp.async.wait_group %0;" :: "n"(N) : "memory");
}

__device__ __forceinline__ void ldm4(uint32_t& r0, uint32_t& r1, uint32_t& r2,
                                     uint32_t& r3, uint32_t addr) {
    asm volatile("ldmatrix.sync.aligned.m8n8.x4.shared.b16 {%0,%1,%2,%3}, [%4];"
                 : "=r"(r0), "=r"(r1), "=r"(r2), "=r"(r3) : "r"(addr));
}

__device__ __forceinline__ void mma16816(float* c, const uint32_t* a,
                                         uint32_t b0, uint32_t b1) {
    asm volatile(
        "mma.sync.aligned.m16n8k16.row.col.f32.f16.f16.f32 "
        "{%0,%1,%2,%3}, {%4,%5,%6,%7}, {%8,%9}, {%0,%1,%2,%3};"
        : "+f"(c[0]), "+f"(c[1]), "+f"(c[2]), "+f"(c[3])
        : "r"(a[0]), "r"(a[1]), "r"(a[2]), "r"(a[3]), "r"(b0), "r"(b1));
}

// ---------------------------------------------------------------------------
// Tiling constants
// ---------------------------------------------------------------------------
#define ROWB 80                     // smem row stride bytes (32 h16 = 64B data + 16B pad)
#define TILEB (128 * ROWB)          // 10240 B per 128x32 tile
#define STG   (3 * TILEB)           // Ah, Al, Bh per stage (all GEMMs 2-pass now)
static constexpr unsigned SMEM_BYTES = 2 * STG;   // 61440; >= 34816 mode-1 epilogue stage

// ---------------------------------------------------------------------------
// HMMA GEMM, 2-pass fp16 split: C = Ah@Bh^T + Al@Bh^T  (= (Ah+Al)@Bh^T)
// Operands K-major (ld 2048).
//   MODE 0: projection -> out h16 row-major [8192,2048]; SLO: also store lo
//   MODE 1: projection -> out h16 transposed per batch (V^T), hi only
//   MODE 2: scores     -> out fp32 * scale, per batch, causal tile skip
//   MODE 3: attn @ V^T -> out fp32 per batch, causal K bound
// ---------------------------------------------------------------------------
template<int MODE, bool SLO>
__global__ __launch_bounds__(256, 2)
void mma_gemm(const h16* __restrict__ Ahi, const h16* __restrict__ Alo,
              const h16* __restrict__ Bhi,
              float* __restrict__ out_f,
              h16* __restrict__ out_hi, h16* __restrict__ out_lo,
              float scale)
{
    const int bx = blockIdx.x, by = blockIdx.y, bz = blockIdx.z;
    if (MODE == 2 && bx > by) return;     // fully masked score tile

    extern __shared__ char smem[];
    const uint32_t sbase = smem_u32(smem);

    const int tid    = threadIdx.x;
    const int wid    = tid >> 5;
    const int lane   = tid & 31;
    const int warp_m = wid & 3;           // 4 x 32 rows
    const int warp_n = wid >> 2;          // 2 x 64 cols

    const size_t boff_mat = (MODE >= 2) ? (size_t)bz * 2048 * 2048 : 0;

    const h16* Ah = Ahi + boff_mat + (size_t)(by * 128) * 2048;
    const h16* Al = Alo + boff_mat + (size_t)(by * 128) * 2048;
    const h16* Bh = Bhi + boff_mat + (size_t)(bx * 128) * 2048;

    const int nk = (MODE == 3) ? (by + 1) * 4 : 64;   // number of 32-wide K chunks

    // loader: thread t covers rows (t>>2) and (t>>2)+64, 16B chunk (t&3)
    const int lrow = tid >> 2;
    const int lcb  = (tid & 3) * 16;

    auto load_stage = [&](int kc) {
        const uint32_t sd = sbase + (kc & 1) * STG;
        const size_t goff = (size_t)kc * 32;           // element offset in K
        const char* pa0 = (const char*)(Ah + goff);
        const char* pa1 = (const char*)(Al + goff);
        const char* pb0 = (const char*)(Bh + goff);
#pragma unroll
        for (int i = 0; i < 2; ++i) {
            const int r = lrow + i * 64;
            const uint32_t so = (uint32_t)r * ROWB + lcb;
            const size_t go = (size_t)r * 4096 + lcb;  // 2048 elems * 2B
            cp16(sd + 0 * TILEB + so, pa0 + go);
            cp16(sd + 1 * TILEB + so, pa1 + go);
            cp16(sd + 2 * TILEB + so, pb0 + go);
        }
        cp_commit();
    };

    float acc[2][8][4] = {};

    load_stage(0);

    for (int s = 0; s < nk; ++s) {
        if (s + 1 < nk) { load_stage(s + 1); cp_wait<1>(); }
        else            { cp_wait<0>(); }
        __syncthreads();

        const uint32_t sd = sbase + (s & 1) * STG;
        const uint32_t lrh = (uint32_t)(lane & 15) * ROWB + (uint32_t)(lane >> 4) * 16;

        // two k16 halves per 32-wide chunk
#pragma unroll
        for (int half = 0; half < 2; ++half) {
            const uint32_t hb = lrh + (uint32_t)half * 32;   // byte offset of k-half

            uint32_t ah[2][4], al2[2][4], bh[4][4];
#pragma unroll
            for (int mt = 0; mt < 2; ++mt) {
                const uint32_t ro = (uint32_t)(warp_m * 32 + mt * 16) * ROWB + hb;
                ldm4(ah[mt][0],  ah[mt][1],  ah[mt][2],  ah[mt][3],  sd + 0 * TILEB + ro);
                ldm4(al2[mt][0], al2[mt][1], al2[mt][2], al2[mt][3], sd + 1 * TILEB + ro);
            }
#pragma unroll
            for (int g = 0; g < 4; ++g) {
                const uint32_t ro = (uint32_t)(warp_n * 64 + g * 16) * ROWB + hb;
                ldm4(bh[g][0], bh[g][1], bh[g][2], bh[g][3], sd + 2 * TILEB + ro);
            }

#pragma unroll
            for (int mt = 0; mt < 2; ++mt)
#pragma unroll
                for (int nt = 0; nt < 8; ++nt) {
                    const int g = nt >> 1, o = nt & 1;
                    mma16816(acc[mt][nt], ah[mt],  bh[g][o], bh[g][2 + o]);
                    mma16816(acc[mt][nt], al2[mt], bh[g][o], bh[g][2 + o]);
                }
        }
        __syncthreads();
    }

    // ---- epilogue ----
    const int tq = lane >> 2;      // row within 8
    const int tr = lane & 3;       // col pair

    if (MODE == 1) {
        // stage hi tile in smem, then coalesced transposed write (hi only)
#pragma unroll
        for (int mt = 0; mt < 2; ++mt)
#pragma unroll
            for (int nt = 0; nt < 8; ++nt) {
                const int ml = warp_m * 32 + mt * 16 + tq;
                const int nl = warp_n * 64 + nt * 8 + tr * 2;
#pragma unroll
                for (int h = 0; h < 2; ++h) {
                    const float c0 = acc[mt][nt][h * 2 + 0];
                    const float c1 = acc[mt][nt][h * 2 + 1];
                    const uint32_t so = (uint32_t)(ml + h * 8) * 272 + (uint32_t)nl * 2;
                    *(__half2*)(smem + so) =
                        __halves2half2(__float2half_rn(c0), __float2half_rn(c1));
                }
            }
        __syncthreads();
        // token rows of this tile are one contiguous st-range of one batch
        const int b   = by >> 4;
        const int st0 = (by & 15) * 128;
        const int nl  = tid >> 1;          // 0..127 (output row = dim index)
        const int hh  = tid & 1;           // which 64-token half
        const size_t obase = ((size_t)b * 2048 + bx * 128 + nl) * 2048 + st0 + hh * 64;
#pragma unroll 4
        for (int j = 0; j < 64; j += 2) {
            const uint32_t s0 = (uint32_t)(hh * 64 + j) * 272 + (uint32_t)nl * 2;
            h16 a0 = *(const h16*)(smem + s0);
            h16 a1 = *(const h16*)(smem + s0 + 272);
            *(__half2*)(out_hi + obase + j) = __halves2half2(a0, a1);
        }
        return;
    }

#pragma unroll
    for (int mt = 0; mt < 2; ++mt)
#pragma unroll
        for (int nt = 0; nt < 8; ++nt) {
            const int gm = by * 128 + warp_m * 32 + mt * 16 + tq;
            const int gn = bx * 128 + warp_n * 64 + nt * 8 + tr * 2;
#pragma unroll
            for (int h = 0; h < 2; ++h) {
                const float c0 = acc[mt][nt][h * 2 + 0];
                const float c1 = acc[mt][nt][h * 2 + 1];
                if (MODE == 0) {
                    const size_t o = (size_t)(gm + h * 8) * 2048 + gn;
                    const h16 h0 = __float2half_rn(c0);
                    const h16 h1 = __float2half_rn(c1);
                    *(__half2*)(out_hi + o) = __halves2half2(h0, h1);
                    if (SLO)
                        *(__half2*)(out_lo + o) = __halves2half2(
                            __float2half_rn(c0 - __half2float(h0)),
                            __float2half_rn(c1 - __half2float(h1)));
                } else {
                    const float sc = (MODE == 2) ? scale : 1.0f;
                    const size_t o = (size_t)bz * 2048 * 2048 + (size_t)(gm + h * 8) * 2048 + gn;
                    *(float2*)(out_f + o) = make_float2(c0 * sc, c1 * sc);
                }
            }
        }
}

// ---------------------------------------------------------------------------
// fp32 -> (fp16 hi, fp16 lo) split, and hi-only variant (for weights)
// ---------------------------------------------------------------------------
__global__ void split_kernel(const float* __restrict__ s,
                             h16* __restrict__ hi, h16* __restrict__ lo, int n)
{
    int i = blockIdx.x * blockDim.x + threadIdx.x;
    if (i < n) {
        float v = s[i];
        h16 h = __float2half_rn(v);
        hi[i] = h;
        lo[i] = __float2half_rn(v - __half2float(h));
    }
}

__global__ void split_hi_kernel(const float* __restrict__ s,
                                h16* __restrict__ hi, int n)
{
    int i = blockIdx.x * blockDim.x + threadIdx.x;
    if (i < n) hi[i] = __float2half_rn(s[i]);
}

// ---------------------------------------------------------------------------
// Causal softmax: fp32 scores (k<=q valid) -> attn hi/lo fp16, zero above diag
// ---------------------------------------------------------------------------
__global__ void softmax_kernel(const float* __restrict__ S,
                               h16* __restrict__ Phi, h16* __restrict__ Plo)
{
    const int row = blockIdx.x;
    const int b = row / SEQ;
    const int q = row % SEQ;
    const float* sr = S + ((size_t)b * SEQ + q) * SEQ;
    const size_t ob = ((size_t)b * SEQ + q) * SEQ;
    const int len = q + 1;

    __shared__ float sh[8];

    float m = -1e30f;
    for (int k = threadIdx.x; k < len; k += blockDim.x)
        m = fmaxf(m, sr[k]);
#pragma unroll
    for (int o = 16; o; o >>= 1)
        m = fmaxf(m, __shfl_xor_sync(0xffffffffu, m, o));
    if ((threadIdx.x & 31) == 0) sh[threadIdx.x >> 5] = m;
    __syncthreads();
    m = sh[0];
#pragma unroll
    for (int w = 1; w < 8; ++w) m = fmaxf(m, sh[w]);

    float sum = 0.f;
    for (int k = threadIdx.x; k < len; k += blockDim.x)
        sum += __expf(sr[k] - m);
#pragma unroll
    for (int o = 16; o; o >>= 1)
        sum += __shfl_xor_sync(0xffffffffu, sum, o);
    __syncthreads();
    if ((threadIdx.x & 31) == 0) sh[threadIdx.x >> 5] = sum;
    __syncthreads();
    sum = 0.f;
#pragma unroll
    for (int w = 0; w < 8; ++w) sum += sh[w];

    const float inv = 1.0f / sum;
    for (int k = threadIdx.x; k < SEQ; k += blockDim.x) {
        if (k < len) {
            float a = __expf(sr[k] - m) * inv;
            h16 h = __float2half_rn(a);
            Phi[ob + k] = h;
            Plo[ob + k] = __float2half_rn(a - __half2float(h));
        } else {
            Phi[ob + k] = __float2half_rn(0.f);
            Plo[ob + k] = __float2half_rn(0.f);
        }
    }
}

// ---------------------------------------------------------------------------
extern "C" void kernel_launch(void* const* d_in, const int* in_sizes, int n_in,
                              void* d_out, int out_size)
{
    const float* x  = (const float*)d_in[0];
    const float* Wk = (const float*)d_in[1];
    const float* Wq = (const float*)d_in[2];
    const float* Wv = (const float*)d_in[3];
    float* out = (float*)d_out;

    h16 *xhi, *xlo, *wqh, *wkh, *wvh;
    h16 *qhi, *qlo, *khi, *vthi, *phi, *plo;
    float* s;
    cudaGetSymbolAddress((void**)&xhi,  g_xhi);
    cudaGetSymbolAddress((void**)&xlo,  g_xlo);
    cudaGetSymbolAddress((void**)&wqh,  g_Wqhi);
    cudaGetSymbolAddress((void**)&wkh,  g_Wkhi);
    cudaGetSymbolAddress((void**)&wvh,  g_Wvhi);
    cudaGetSymbolAddress((void**)&qhi,  g_Qhi);
    cudaGetSymbolAddress((void**)&qlo,  g_Qlo);
    cudaGetSymbolAddress((void**)&khi,  g_Khi);
    cudaGetSymbolAddress((void**)&vthi, g_Vthi);
    cudaGetSymbolAddress((void**)&phi,  g_Phi);
    cudaGetSymbolAddress((void**)&plo,  g_Plo);
    cudaGetSymbolAddress((void**)&s,    g_S);

    cudaFuncSetAttribute((const void*)mma_gemm<0,true>,  cudaFuncAttributeMaxDynamicSharedMemorySize, SMEM_BYTES);
    cudaFuncSetAttribute((const void*)mma_gemm<0,false>, cudaFuncAttributeMaxDynamicSharedMemorySize, SMEM_BYTES);
    cudaFuncSetAttribute((const void*)mma_gemm<1,false>, cudaFuncAttributeMaxDynamicSharedMemorySize, SMEM_BYTES);
    cudaFuncSetAttribute((const void*)mma_gemm<2,false>, cudaFuncAttributeMaxDynamicSharedMemorySize, SMEM_BYTES);
    cudaFuncSetAttribute((const void*)mma_gemm<3,false>, cudaFuncAttributeMaxDynamicSharedMemorySize, SMEM_BYTES);

    const float inv_scale = 1.0f / sqrtf((float)DIM);

    {
        int n = BATCH * SEQ * EMB;
        split_kernel<<<(n + 255) / 256, 256>>>(x, xhi, xlo, n);
        int nw = DIM * EMB;
        split_hi_kernel<<<(nw + 255) / 256, 256>>>(Wq, wqh, nw);
        split_hi_kernel<<<(nw + 255) / 256, 256>>>(Wk, wkh, nw);
        split_hi_kernel<<<(nw + 255) / 256, 256>>>(Wv, wvh, nw);
    }

    dim3 blk(256);
    dim3 gproj(DIM / 128, (BATCH * SEQ) / 128);         // 16 x 64
    mma_gemm<0,true ><<<gproj, blk, SMEM_BYTES>>>(xhi, xlo, wqh, nullptr, qhi, qlo, 0.f);
    mma_gemm<0,false><<<gproj, blk, SMEM_BYTES>>>(xhi, xlo, wkh, nullptr, khi, nullptr, 0.f);
    mma_gemm<1,false><<<gproj, blk, SMEM_BYTES>>>(xhi, xlo, wvh, nullptr, vthi, nullptr, 0.f);

    dim3 gattn(SEQ / 128, SEQ / 128, BATCH);            // 16 x 16 x 4
    mma_gemm<2,false><<<gattn, blk, SMEM_BYTES>>>(qhi, qlo, khi, s, nullptr, nullptr, inv_scale);

    softmax_kernel<<<BATCH * SEQ, 256>>>(s, phi, plo);

    mma_gemm<3,false><<<gattn, blk, SMEM_BYTES>>>(phi, plo, vthi, out, nullptr, nullptr, 0.f);
}

// round 11
// speedup vs baseline: 3.9276x; 1.1561x over previous
#include <cuda_runtime.h>
#include <cuda_fp16.h>
#include <math.h>
#include <stdint.h>

#define SEQ   2048
#define EMB   2048
#define DIM   2048
#define BATCH 4

typedef __half h16;

// ---------------------------------------------------------------------------
// Device scratch (no cudaMalloc allowed anywhere)
// ---------------------------------------------------------------------------
__device__ h16 g_xhi[(size_t)BATCH * SEQ * EMB];
__device__ h16 g_xlo[(size_t)BATCH * SEQ * EMB];
__device__ h16 g_Wqhi[(size_t)DIM * EMB];
__device__ h16 g_Wkhi[(size_t)DIM * EMB];
__device__ h16 g_Wvhi[(size_t)DIM * EMB];
__device__ h16 g_Qhi[(size_t)BATCH * SEQ * DIM];
__device__ h16 g_Khi[(size_t)BATCH * SEQ * DIM];
__device__ h16 g_Vthi[(size_t)BATCH * DIM * SEQ];   // V^T per batch, hi only
__device__ float g_S [(size_t)BATCH * SEQ * SEQ];
__device__ h16 g_Phi[(size_t)BATCH * SEQ * SEQ];

// ---------------------------------------------------------------------------
// PTX helpers (sm_80-level PTX only; no arch-suffixed instructions)
// ---------------------------------------------------------------------------
__device__ __forceinline__ uint32_t smem_u32(const void* p) {
    uint32_t a;
    asm("{ .reg .u64 t; cvta.to.shared.u64 t, %1; cvt.u32.u64 %0, t; }"
        : "=r"(a) : "l"(p));
    return a;
}

__device__ __forceinline__ void cp16(uint32_t dst, const void* src) {
    asm volatile("cp.async.cg.shared.global [%0], [%1], 16;" :: "r"(dst), "l"(src));
}
__device__ __forceinline__ void cp_commit() {
    asm volatile("cp.async.commit_group;" ::: "memory");
}
template<int N> __device__ __forceinline__ void cp_wait() {
    asm volatile("cp.async.wait_group %0;" :: "n"(N) : "memory");
}

__device__ __forceinline__ void ldm4(uint32_t& r0, uint32_t& r1, uint32_t& r2,
                                     uint32_t& r3, uint32_t addr) {
    asm volatile("ldmatrix.sync.aligned.m8n8.x4.shared.b16 {%0,%1,%2,%3}, [%4];"
                 : "=r"(r0), "=r"(r1), "=r"(r2), "=r"(r3) : "r"(addr));
}

__device__ __forceinline__ void mma16816(float* c, const uint32_t* a,
                                         uint32_t b0, uint32_t b1) {
    asm volatile(
        "mma.sync.aligned.m16n8k16.row.col.f32.f16.f16.f32 "
        "{%0,%1,%2,%3}, {%4,%5,%6,%7}, {%8,%9}, {%0,%1,%2,%3};"
        : "+f"(c[0]), "+f"(c[1]), "+f"(c[2]), "+f"(c[3])
        : "r"(a[0]), "r"(a[1]), "r"(a[2]), "r"(a[3]), "r"(b0), "r"(b1));
}

// ---------------------------------------------------------------------------
// Tiling constants
// ---------------------------------------------------------------------------
#define ROWB 80                     // smem row stride bytes (32 h16 = 64B data + 16B pad)
#define TILEB (128 * ROWB)          // 10240 B per 128x32 tile
static constexpr unsigned SMEM_P2 = 2 * 3 * TILEB;   // 61440 (2-pass: Ah, Al, Bh)
static constexpr unsigned SMEM_P1 = 2 * 2 * TILEB;   // 40960 (1-pass: A, B)

// ---------------------------------------------------------------------------
// HMMA GEMM, fp16, operands K-major (ld 2048).
//   NPASS=2: C = (Ah + Al) @ Bh^T   (tiles: Ah, Al, Bh)
//   NPASS=1: C = A @ B^T            (tiles: A, B)
//   MODE 0: projection -> out h16 row-major [8192, 2048]
//   MODE 1: projection -> out h16 transposed per batch (V^T)
//   MODE 2: scores     -> out fp32 * scale, per batch, causal tile skip
//   MODE 3: attn @ V^T -> out fp32 per batch, causal K bound
// ---------------------------------------------------------------------------
template<int MODE, int NPASS>
__global__ __launch_bounds__(256, 2)
void mma_gemm(const h16* __restrict__ Ahi, const h16* __restrict__ Alo,
              const h16* __restrict__ Bhi,
              float* __restrict__ out_f, h16* __restrict__ out_hi,
              float scale)
{
    constexpr int NT = (NPASS == 2) ? 3 : 2;        // tiles per stage
    constexpr int BT = NT - 1;                       // B tile index
    constexpr uint32_t STG = NT * TILEB;

    const int bx = blockIdx.x, by = blockIdx.y, bz = blockIdx.z;
    if (MODE == 2 && bx > by) return;     // fully masked score tile

    extern __shared__ char smem[];
    const uint32_t sbase = smem_u32(smem);

    const int tid    = threadIdx.x;
    const int wid    = tid >> 5;
    const int lane   = tid & 31;
    const int warp_m = wid & 3;           // 4 x 32 rows
    const int warp_n = wid >> 2;          // 2 x 64 cols

    const size_t boff_mat = (MODE >= 2) ? (size_t)bz * 2048 * 2048 : 0;

    const h16* Ah = Ahi + boff_mat + (size_t)(by * 128) * 2048;
    const h16* Al = (NPASS == 2) ? Alo + (size_t)(by * 128) * 2048 : nullptr;
    const h16* Bh = Bhi + boff_mat + (size_t)(bx * 128) * 2048;

    const int nk = (MODE == 3) ? (by + 1) * 4 : 64;   // number of 32-wide K chunks

    // loader: thread t covers rows (t>>2) and (t>>2)+64, 16B chunk (t&3)
    const int lrow = tid >> 2;
    const int lcb  = (tid & 3) * 16;

    auto load_stage = [&](int kc) {
        const uint32_t sd = sbase + (kc & 1) * STG;
        const size_t goff = (size_t)kc * 32;           // element offset in K
        const char* pa0 = (const char*)(Ah + goff);
        const char* pa1 = (NPASS == 2) ? (const char*)(Al + goff) : nullptr;
        const char* pb0 = (const char*)(Bh + goff);
#pragma unroll
        for (int i = 0; i < 2; ++i) {
            const int r = lrow + i * 64;
            const uint32_t so = (uint32_t)r * ROWB + lcb;
            const size_t go = (size_t)r * 4096 + lcb;  // 2048 elems * 2B
            cp16(sd + 0 * TILEB + so, pa0 + go);
            if (NPASS == 2) cp16(sd + 1 * TILEB + so, pa1 + go);
            cp16(sd + BT * TILEB + so, pb0 + go);
        }
        cp_commit();
    };

    float acc[2][8][4] = {};

    load_stage(0);

    for (int s = 0; s < nk; ++s) {
        if (s + 1 < nk) { load_stage(s + 1); cp_wait<1>(); }
        else            { cp_wait<0>(); }
        __syncthreads();

        const uint32_t sd = sbase + (s & 1) * STG;
        const uint32_t lrh = (uint32_t)(lane & 15) * ROWB + (uint32_t)(lane >> 4) * 16;

        // two k16 halves per 32-wide chunk
#pragma unroll
        for (int half = 0; half < 2; ++half) {
            const uint32_t hb = lrh + (uint32_t)half * 32;   // byte offset of k-half

            uint32_t ah[2][4], al2[2][4], bh[4][4];
#pragma unroll
            for (int mt = 0; mt < 2; ++mt) {
                const uint32_t ro = (uint32_t)(warp_m * 32 + mt * 16) * ROWB + hb;
                ldm4(ah[mt][0], ah[mt][1], ah[mt][2], ah[mt][3], sd + 0 * TILEB + ro);
                if (NPASS == 2)
                    ldm4(al2[mt][0], al2[mt][1], al2[mt][2], al2[mt][3],
                         sd + 1 * TILEB + ro);
            }
#pragma unroll
            for (int g = 0; g < 4; ++g) {
                const uint32_t ro = (uint32_t)(warp_n * 64 + g * 16) * ROWB + hb;
                ldm4(bh[g][0], bh[g][1], bh[g][2], bh[g][3], sd + BT * TILEB + ro);
            }

#pragma unroll
            for (int mt = 0; mt < 2; ++mt)
#pragma unroll
                for (int nt = 0; nt < 8; ++nt) {
                    const int g = nt >> 1, o = nt & 1;
                    mma16816(acc[mt][nt], ah[mt], bh[g][o], bh[g][2 + o]);
                    if (NPASS == 2)
                        mma16816(acc[mt][nt], al2[mt], bh[g][o], bh[g][2 + o]);
                }
        }
        __syncthreads();
    }

    // ---- epilogue ----
    const int tq = lane >> 2;      // row within 8
    const int tr = lane & 3;       // col pair

    if (MODE == 1) {
        // stage hi tile in smem, then coalesced transposed write
#pragma unroll
        for (int mt = 0; mt < 2; ++mt)
#pragma unroll
            for (int nt = 0; nt < 8; ++nt) {
                const int ml = warp_m * 32 + mt * 16 + tq;
                const int nl = warp_n * 64 + nt * 8 + tr * 2;
#pragma unroll
                for (int h = 0; h < 2; ++h) {
                    const float c0 = acc[mt][nt][h * 2 + 0];
                    const float c1 = acc[mt][nt][h * 2 + 1];
                    const uint32_t so = (uint32_t)(ml + h * 8) * 272 + (uint32_t)nl * 2;
                    *(__half2*)(smem + so) =
                        __halves2half2(__float2half_rn(c0), __float2half_rn(c1));
                }
            }
        __syncthreads();
        // token rows of this tile are one contiguous st-range of one batch
        const int b   = by >> 4;
        const int st0 = (by & 15) * 128;
        const int nl  = tid >> 1;          // 0..127 (output row = dim index)
        const int hh  = tid & 1;           // which 64-token half
        const size_t obase = ((size_t)b * 2048 + bx * 128 + nl) * 2048 + st0 + hh * 64;
#pragma unroll 4
        for (int j = 0; j < 64; j += 2) {
            const uint32_t s0 = (uint32_t)(hh * 64 + j) * 272 + (uint32_t)nl * 2;
            h16 a0 = *(const h16*)(smem + s0);
            h16 a1 = *(const h16*)(smem + s0 + 272);
            *(__half2*)(out_hi + obase + j) = __halves2half2(a0, a1);
        }
        return;
    }

#pragma unroll
    for (int mt = 0; mt < 2; ++mt)
#pragma unroll
        for (int nt = 0; nt < 8; ++nt) {
            const int gm = by * 128 + warp_m * 32 + mt * 16 + tq;
            const int gn = bx * 128 + warp_n * 64 + nt * 8 + tr * 2;
#pragma unroll
            for (int h = 0; h < 2; ++h) {
                const float c0 = acc[mt][nt][h * 2 + 0];
                const float c1 = acc[mt][nt][h * 2 + 1];
                if (MODE == 0) {
                    const size_t o = (size_t)(gm + h * 8) * 2048 + gn;
                    *(__half2*)(out_hi + o) =
                        __halves2half2(__float2half_rn(c0), __float2half_rn(c1));
                } else {
                    const float sc = (MODE == 2) ? scale : 1.0f;
                    const size_t o = (size_t)bz * 2048 * 2048 + (size_t)(gm + h * 8) * 2048 + gn;
                    *(float2*)(out_f + o) = make_float2(c0 * sc, c1 * sc);
                }
            }
        }
}

// ---------------------------------------------------------------------------
// fp32 -> (fp16 hi, fp16 lo) split, and hi-only variant (for weights)
// ---------------------------------------------------------------------------
__global__ void split_kernel(const float* __restrict__ s,
                             h16* __restrict__ hi, h16* __restrict__ lo, int n)
{
    int i = blockIdx.x * blockDim.x + threadIdx.x;
    if (i < n) {
        float v = s[i];
        h16 h = __float2half_rn(v);
        hi[i] = h;
        lo[i] = __float2half_rn(v - __half2float(h));
    }
}

__global__ void split_hi_kernel(const float* __restrict__ s,
                                h16* __restrict__ hi, int n)
{
    int i = blockIdx.x * blockDim.x + threadIdx.x;
    if (i < n) hi[i] = __float2half_rn(s[i]);
}

// ---------------------------------------------------------------------------
// Causal softmax: fp32 scores (k<=q valid) -> attn fp16 (hi only).
// Row cached in smem: one global read, one exp pass.
// Writes only k < klim (128-aligned tile bound); AV never reads beyond.
// ---------------------------------------------------------------------------
__global__ void softmax_kernel(const float* __restrict__ S,
                               h16* __restrict__ Phi)
{
    const int row = blockIdx.x;
    const int b = row >> 11;
    const int q = row & 2047;
    const float* sr = S + ((size_t)b * SEQ + q) * SEQ;
    const size_t ob = ((size_t)b * SEQ + q) * SEQ;
    const int len  = q + 1;
    const int klim = ((q >> 7) + 1) << 7;     // 128-aligned upper bound

    __shared__ float buf[SEQ];
    __shared__ float red[8];

    // pass 1: load row into smem, running max
    float m = -1e30f;
    for (int k = threadIdx.x; k < len; k += blockDim.x) {
        float v = sr[k];
        buf[k] = v;
        m = fmaxf(m, v);
    }
#pragma unroll
    for (int o = 16; o; o >>= 1)
        m = fmaxf(m, __shfl_xor_sync(0xffffffffu, m, o));
    if ((threadIdx.x & 31) == 0) red[threadIdx.x >> 5] = m;
    __syncthreads();
    m = red[0];
#pragma unroll
    for (int w = 1; w < 8; ++w) m = fmaxf(m, red[w]);

    // pass 2: exp in smem, running sum
    float sum = 0.f;
    for (int k = threadIdx.x; k < len; k += blockDim.x) {
        float e = __expf(buf[k] - m);
        buf[k] = e;
        sum += e;
    }
#pragma unroll
    for (int o = 16; o; o >>= 1)
        sum += __shfl_xor_sync(0xffffffffu, sum, o);
    __syncthreads();
    if ((threadIdx.x & 31) == 0) red[threadIdx.x >> 5] = sum;
    __syncthreads();
    sum = 0.f;
#pragma unroll
    for (int w = 0; w < 8; ++w) sum += red[w];

    const float inv = 1.0f / sum;

    // pass 3: normalized fp16 writes, paired (klim is even)
    for (int k = threadIdx.x * 2; k < klim; k += blockDim.x * 2) {
        float a0 = (k     < len) ? buf[k]     * inv : 0.f;
        float a1 = (k + 1 < len) ? buf[k + 1] * inv : 0.f;
        *(__half2*)(Phi + ob + k) =
            __halves2half2(__float2half_rn(a0), __float2half_rn(a1));
    }
}

// ---------------------------------------------------------------------------
extern "C" void kernel_launch(void* const* d_in, const int* in_sizes, int n_in,
                              void* d_out, int out_size)
{
    const float* x  = (const float*)d_in[0];
    const float* Wk = (const float*)d_in[1];
    const float* Wq = (const float*)d_in[2];
    const float* Wv = (const float*)d_in[3];
    float* out = (float*)d_out;

    h16 *xhi, *xlo, *wqh, *wkh, *wvh;
    h16 *qhi, *khi, *vthi, *phi;
    float* s;
    cudaGetSymbolAddress((void**)&xhi,  g_xhi);
    cudaGetSymbolAddress((void**)&xlo,  g_xlo);
    cudaGetSymbolAddress((void**)&wqh,  g_Wqhi);
    cudaGetSymbolAddress((void**)&wkh,  g_Wkhi);
    cudaGetSymbolAddress((void**)&wvh,  g_Wvhi);
    cudaGetSymbolAddress((void**)&qhi,  g_Qhi);
    cudaGetSymbolAddress((void**)&khi,  g_Khi);
    cudaGetSymbolAddress((void**)&vthi, g_Vthi);
    cudaGetSymbolAddress((void**)&phi,  g_Phi);
    cudaGetSymbolAddress((void**)&s,    g_S);

    cudaFuncSetAttribute((const void*)mma_gemm<0,2>, cudaFuncAttributeMaxDynamicSharedMemorySize, SMEM_P2);
    cudaFuncSetAttribute((const void*)mma_gemm<1,2>, cudaFuncAttributeMaxDynamicSharedMemorySize, SMEM_P2);
    cudaFuncSetAttribute((const void*)mma_gemm<2,1>, cudaFuncAttributeMaxDynamicSharedMemorySize, SMEM_P1);
    cudaFuncSetAttribute((const void*)mma_gemm<3,1>, cudaFuncAttributeMaxDynamicSharedMemorySize, SMEM_P1);

    const float inv_scale = 1.0f / sqrtf((float)DIM);

    {
        int n = BATCH * SEQ * EMB;
        split_kernel<<<(n + 255) / 256, 256>>>(x, xhi, xlo, n);
        int nw = DIM * EMB;
        split_hi_kernel<<<(nw + 255) / 256, 256>>>(Wq, wqh, nw);
        split_hi_kernel<<<(nw + 255) / 256, 256>>>(Wk, wkh, nw);
        split_hi_kernel<<<(nw + 255) / 256, 256>>>(Wv, wvh, nw);
    }

    dim3 blk(256);
    dim3 gproj(DIM / 128, (BATCH * SEQ) / 128);         // 16 x 64
    mma_gemm<0,2><<<gproj, blk, SMEM_P2>>>(xhi, xlo, wqh, nullptr, qhi, 0.f);
    mma_gemm<0,2><<<gproj, blk, SMEM_P2>>>(xhi, xlo, wkh, nullptr, khi, 0.f);
    mma_gemm<1,2><<<gproj, blk, SMEM_P2>>>(xhi, xlo, wvh, nullptr, vthi, 0.f);

    dim3 gattn(SEQ / 128, SEQ / 128, BATCH);            // 16 x 16 x 4
    mma_gemm<2,1><<<gattn, blk, SMEM_P1>>>(qhi, nullptr, khi, s, nullptr, inv_scale);

    softmax_kernel<<<BATCH * SEQ, 256>>>(s, phi);

    mma_gemm<3,1><<<gattn, blk, SMEM_P1>>>(phi, nullptr, vthi, out, nullptr, 0.f);
}

// round 12
// speedup vs baseline: 5.8673x; 1.4939x over previous
#include <cuda_runtime.h>
#include <cuda_fp16.h>
#include <math.h>
#include <stdint.h>

#define SEQ   2048
#define EMB   2048
#define DIM   2048
#define BATCH 4

typedef __half h16;

// ---------------------------------------------------------------------------
// Device scratch (no cudaMalloc allowed anywhere)
// ---------------------------------------------------------------------------
__device__ h16 g_xhi[(size_t)BATCH * SEQ * EMB];
__device__ h16 g_Wqhi[(size_t)DIM * EMB];
__device__ h16 g_Wkhi[(size_t)DIM * EMB];
__device__ h16 g_Wvhi[(size_t)DIM * EMB];
__device__ h16 g_Qhi[(size_t)BATCH * SEQ * DIM];
__device__ h16 g_Khi[(size_t)BATCH * SEQ * DIM];
__device__ h16 g_Vthi[(size_t)BATCH * DIM * SEQ];   // V^T per batch
__device__ float g_S [(size_t)BATCH * SEQ * SEQ];
__device__ h16 g_Phi[(size_t)BATCH * SEQ * SEQ];

// ---------------------------------------------------------------------------
// PTX helpers (sm_80-level PTX only; no arch-suffixed instructions)
// ---------------------------------------------------------------------------
__device__ __forceinline__ uint32_t smem_u32(const void* p) {
    uint32_t a;
    asm("{ .reg .u64 t; cvta.to.shared.u64 t, %1; cvt.u32.u64 %0, t; }"
        : "=r"(a) : "l"(p));
    return a;
}

__device__ __forceinline__ void cp16(uint32_t dst, const void* src) {
    asm volatile("cp.async.cg.shared.global [%0], [%1], 16;" :: "r"(dst), "l"(src));
}
__device__ __forceinline__ void cp_commit() {
    asm volatile("cp.async.commit_group;" ::: "memory");
}
template<int N> __device__ __forceinline__ void cp_wait() {
    asm volatile("cp.async.wait_group %0;" :: "n"(N) : "memory");
}

__device__ __forceinline__ void ldm4(uint32_t& r0, uint32_t& r1, uint32_t& r2,
                                     uint32_t& r3, uint32_t addr) {
    asm volatile("ldmatrix.sync.aligned.m8n8.x4.shared.b16 {%0,%1,%2,%3}, [%4];"
                 : "=r"(r0), "=r"(r1), "=r"(r2), "=r"(r3) : "r"(addr));
}

__device__ __forceinline__ void mma16816(float* c, const uint32_t* a,
                                         uint32_t b0, uint32_t b1) {
    asm volatile(
        "mma.sync.aligned.m16n8k16.row.col.f32.f16.f16.f32 "
        "{%0,%1,%2,%3}, {%4,%5,%6,%7}, {%8,%9}, {%0,%1,%2,%3};"
        : "+f"(c[0]), "+f"(c[1]), "+f"(c[2]), "+f"(c[3])
        : "r"(a[0]), "r"(a[1]), "r"(a[2]), "r"(a[3]), "r"(b0), "r"(b1));
}

// ---------------------------------------------------------------------------
// Tiling constants
// ---------------------------------------------------------------------------
#define ROWB 80                     // smem row stride bytes (32 h16 = 64B data + 16B pad)
#define TILEB (128 * ROWB)          // 10240 B per 128x32 tile
#define STG   (2 * TILEB)           // A, B per stage (all GEMMs 1-pass fp16)
static constexpr unsigned SMEM_BYTES = 2 * STG;   // 40960; >= 34816 mode-1 epilogue stage

// ---------------------------------------------------------------------------
// HMMA GEMM, 1-pass fp16: C = A @ B^T. Operands K-major (ld 2048).
//   MODE 0: projection -> out h16 row-major [8192, 2048]
//   MODE 1: projection -> out h16 transposed per batch (V^T)
//   MODE 2: scores     -> out fp32 * scale, per batch, causal tile skip
//   MODE 3: attn @ V^T -> out fp32 per batch, causal K bound
// ---------------------------------------------------------------------------
template<int MODE>
__global__ __launch_bounds__(256, 2)
void mma_gemm(const h16* __restrict__ Ahi, const h16* __restrict__ Bhi,
              float* __restrict__ out_f, h16* __restrict__ out_hi,
              float scale)
{
    const int bx = blockIdx.x, by = blockIdx.y, bz = blockIdx.z;
    if (MODE == 2 && bx > by) return;     // fully masked score tile

    extern __shared__ char smem[];
    const uint32_t sbase = smem_u32(smem);

    const int tid    = threadIdx.x;
    const int wid    = tid >> 5;
    const int lane   = tid & 31;
    const int warp_m = wid & 3;           // 4 x 32 rows
    const int warp_n = wid >> 2;          // 2 x 64 cols

    const size_t boff_mat = (MODE >= 2) ? (size_t)bz * 2048 * 2048 : 0;

    const h16* Ah = Ahi + boff_mat + (size_t)(by * 128) * 2048;
    const h16* Bh = Bhi + boff_mat + (size_t)(bx * 128) * 2048;

    const int nk = (MODE == 3) ? (by + 1) * 4 : 64;   // number of 32-wide K chunks

    // loader: thread t covers rows (t>>2) and (t>>2)+64, 16B chunk (t&3)
    const int lrow = tid >> 2;
    const int lcb  = (tid & 3) * 16;

    auto load_stage = [&](int kc) {
        const uint32_t sd = sbase + (kc & 1) * STG;
        const size_t goff = (size_t)kc * 32;           // element offset in K
        const char* pa = (const char*)(Ah + goff);
        const char* pb = (const char*)(Bh + goff);
#pragma unroll
        for (int i = 0; i < 2; ++i) {
            const int r = lrow + i * 64;
            const uint32_t so = (uint32_t)r * ROWB + lcb;
            const size_t go = (size_t)r * 4096 + lcb;  // 2048 elems * 2B
            cp16(sd + so,         pa + go);
            cp16(sd + TILEB + so, pb + go);
        }
        cp_commit();
    };

    float acc[2][8][4] = {};

    load_stage(0);

    for (int s = 0; s < nk; ++s) {
        if (s + 1 < nk) { load_stage(s + 1); cp_wait<1>(); }
        else            { cp_wait<0>(); }
        __syncthreads();

        const uint32_t sd = sbase + (s & 1) * STG;
        const uint32_t lrh = (uint32_t)(lane & 15) * ROWB + (uint32_t)(lane >> 4) * 16;

        // two k16 halves per 32-wide chunk
#pragma unroll
        for (int half = 0; half < 2; ++half) {
            const uint32_t hb = lrh + (uint32_t)half * 32;   // byte offset of k-half

            uint32_t ah[2][4], bh[4][4];
#pragma unroll
            for (int mt = 0; mt < 2; ++mt) {
                const uint32_t ro = (uint32_t)(warp_m * 32 + mt * 16) * ROWB + hb;
                ldm4(ah[mt][0], ah[mt][1], ah[mt][2], ah[mt][3], sd + ro);
            }
#pragma unroll
            for (int g = 0; g < 4; ++g) {
                const uint32_t ro = (uint32_t)(warp_n * 64 + g * 16) * ROWB + hb;
                ldm4(bh[g][0], bh[g][1], bh[g][2], bh[g][3], sd + TILEB + ro);
            }

#pragma unroll
            for (int mt = 0; mt < 2; ++mt)
#pragma unroll
                for (int nt = 0; nt < 8; ++nt) {
                    const int g = nt >> 1, o = nt & 1;
                    mma16816(acc[mt][nt], ah[mt], bh[g][o], bh[g][2 + o]);
                }
        }
        __syncthreads();
    }

    // ---- epilogue ----
    const int tq = lane >> 2;      // row within 8
    const int tr = lane & 3;       // col pair

    if (MODE == 1) {
        // stage hi tile in smem, then coalesced transposed write
#pragma unroll
        for (int mt = 0; mt < 2; ++mt)
#pragma unroll
            for (int nt = 0; nt < 8; ++nt) {
                const int ml = warp_m * 32 + mt * 16 + tq;
                const int nl = warp_n * 64 + nt * 8 + tr * 2;
#pragma unroll
                for (int h = 0; h < 2; ++h) {
                    const float c0 = acc[mt][nt][h * 2 + 0];
                    const float c1 = acc[mt][nt][h * 2 + 1];
                    const uint32_t so = (uint32_t)(ml + h * 8) * 272 + (uint32_t)nl * 2;
                    *(__half2*)(smem + so) =
                        __halves2half2(__float2half_rn(c0), __float2half_rn(c1));
                }
            }
        __syncthreads();
        // token rows of this tile are one contiguous st-range of one batch
        const int b   = by >> 4;
        const int st0 = (by & 15) * 128;
        const int nl  = tid >> 1;          // 0..127 (output row = dim index)
        const int hh  = tid & 1;           // which 64-token half
        const size_t obase = ((size_t)b * 2048 + bx * 128 + nl) * 2048 + st0 + hh * 64;
#pragma unroll 4
        for (int j = 0; j < 64; j += 2) {
            const uint32_t s0 = (uint32_t)(hh * 64 + j) * 272 + (uint32_t)nl * 2;
            h16 a0 = *(const h16*)(smem + s0);
            h16 a1 = *(const h16*)(smem + s0 + 272);
            *(__half2*)(out_hi + obase + j) = __halves2half2(a0, a1);
        }
        return;
    }

#pragma unroll
    for (int mt = 0; mt < 2; ++mt)
#pragma unroll
        for (int nt = 0; nt < 8; ++nt) {
            const int gm = by * 128 + warp_m * 32 + mt * 16 + tq;
            const int gn = bx * 128 + warp_n * 64 + nt * 8 + tr * 2;
#pragma unroll
            for (int h = 0; h < 2; ++h) {
                const float c0 = acc[mt][nt][h * 2 + 0];
                const float c1 = acc[mt][nt][h * 2 + 1];
                if (MODE == 0) {
                    const size_t o = (size_t)(gm + h * 8) * 2048 + gn;
                    *(__half2*)(out_hi + o) =
                        __halves2half2(__float2half_rn(c0), __float2half_rn(c1));
                } else {
                    const float sc = (MODE == 2) ? scale : 1.0f;
                    const size_t o = (size_t)bz * 2048 * 2048 + (size_t)(gm + h * 8) * 2048 + gn;
                    *(float2*)(out_f + o) = make_float2(c0 * sc, c1 * sc);
                }
            }
        }
}

// ---------------------------------------------------------------------------
// fp32 -> fp16 rounding
// ---------------------------------------------------------------------------
__global__ void split_hi_kernel(const float* __restrict__ s,
                                h16* __restrict__ hi, int n)
{
    int i = blockIdx.x * blockDim.x + threadIdx.x;
    if (i < n) hi[i] = __float2half_rn(s[i]);
}

// ---------------------------------------------------------------------------
// Causal softmax: fp32 scores (k<=q valid) -> attn fp16.
// Row cached in smem: one global read, one exp pass.
// Writes only k < klim (128-aligned tile bound); AV never reads beyond.
// ---------------------------------------------------------------------------
__global__ void softmax_kernel(const float* __restrict__ S,
                               h16* __restrict__ Phi)
{
    const int row = blockIdx.x;
    const int b = row >> 11;
    const int q = row & 2047;
    const float* sr = S + ((size_t)b * SEQ + q) * SEQ;
    const size_t ob = ((size_t)b * SEQ + q) * SEQ;
    const int len  = q + 1;
    const int klim = ((q >> 7) + 1) << 7;     // 128-aligned upper bound

    __shared__ float buf[SEQ];
    __shared__ float red[8];

    // pass 1: load row into smem, running max
    float m = -1e30f;
    for (int k = threadIdx.x; k < len; k += blockDim.x) {
        float v = sr[k];
        buf[k] = v;
        m = fmaxf(m, v);
    }
#pragma unroll
    for (int o = 16; o; o >>= 1)
        m = fmaxf(m, __shfl_xor_sync(0xffffffffu, m, o));
    if ((threadIdx.x & 31) == 0) red[threadIdx.x >> 5] = m;
    __syncthreads();
    m = red[0];
#pragma unroll
    for (int w = 1; w < 8; ++w) m = fmaxf(m, red[w]);

    // pass 2: exp in smem, running sum
    float sum = 0.f;
    for (int k = threadIdx.x; k < len; k += blockDim.x) {
        float e = __expf(buf[k] - m);
        buf[k] = e;
        sum += e;
    }
#pragma unroll
    for (int o = 16; o; o >>= 1)
        sum += __shfl_xor_sync(0xffffffffu, sum, o);
    __syncthreads();
    if ((threadIdx.x & 31) == 0) red[threadIdx.x >> 5] = sum;
    __syncthreads();
    sum = 0.f;
#pragma unroll
    for (int w = 0; w < 8; ++w) sum += red[w];

    const float inv = 1.0f / sum;

    // pass 3: normalized fp16 writes, paired (klim is even)
    for (int k = threadIdx.x * 2; k < klim; k += blockDim.x * 2) {
        float a0 = (k     < len) ? buf[k]     * inv : 0.f;
        float a1 = (k + 1 < len) ? buf[k + 1] * inv : 0.f;
        *(__half2*)(Phi + ob + k) =
            __halves2half2(__float2half_rn(a0), __float2half_rn(a1));
    }
}

// ---------------------------------------------------------------------------
extern "C" void kernel_launch(void* const* d_in, const int* in_sizes, int n_in,
                              void* d_out, int out_size)
{
    const float* x  = (const float*)d_in[0];
    const float* Wk = (const float*)d_in[1];
    const float* Wq = (const float*)d_in[2];
    const float* Wv = (const float*)d_in[3];
    float* out = (float*)d_out;

    h16 *xhi, *wqh, *wkh, *wvh;
    h16 *qhi, *khi, *vthi, *phi;
    float* s;
    cudaGetSymbolAddress((void**)&xhi,  g_xhi);
    cudaGetSymbolAddress((void**)&wqh,  g_Wqhi);
    cudaGetSymbolAddress((void**)&wkh,  g_Wkhi);
    cudaGetSymbolAddress((void**)&wvh,  g_Wvhi);
    cudaGetSymbolAddress((void**)&qhi,  g_Qhi);
    cudaGetSymbolAddress((void**)&khi,  g_Khi);
    cudaGetSymbolAddress((void**)&vthi, g_Vthi);
    cudaGetSymbolAddress((void**)&phi,  g_Phi);
    cudaGetSymbolAddress((void**)&s,    g_S);

    cudaFuncSetAttribute((const void*)mma_gemm<0>, cudaFuncAttributeMaxDynamicSharedMemorySize, SMEM_BYTES);
    cudaFuncSetAttribute((const void*)mma_gemm<1>, cudaFuncAttributeMaxDynamicSharedMemorySize, SMEM_BYTES);
    cudaFuncSetAttribute((const void*)mma_gemm<2>, cudaFuncAttributeMaxDynamicSharedMemorySize, SMEM_BYTES);
    cudaFuncSetAttribute((const void*)mma_gemm<3>, cudaFuncAttributeMaxDynamicSharedMemorySize, SMEM_BYTES);

    const float inv_scale = 1.0f / sqrtf((float)DIM);

    {
        int n = BATCH * SEQ * EMB;              // 16,777,216
        split_hi_kernel<<<(n + 255) / 256, 256>>>(x, xhi, n);
        int nw = DIM * EMB;                     // 4,194,304
        split_hi_kernel<<<(nw + 255) / 256, 256>>>(Wq, wqh, nw);
        split_hi_kernel<<<(nw + 255) / 256, 256>>>(Wk, wkh, nw);
        split_hi_kernel<<<(nw + 255) / 256, 256>>>(Wv, wvh, nw);
    }

    dim3 blk(256);
    dim3 gproj(DIM / 128, (BATCH * SEQ) / 128);         // 16 x 64
    mma_gemm<0><<<gproj, blk, SMEM_BYTES>>>(xhi, wqh, nullptr, qhi, 0.f);
    mma_gemm<0><<<gproj, blk, SMEM_BYTES>>>(xhi, wkh, nullptr, khi, 0.f);
    mma_gemm<1><<<gproj, blk, SMEM_BYTES>>>(xhi, wvh, nullptr, vthi, 0.f);

    dim3 gattn(SEQ / 128, SEQ / 128, BATCH);            // 16 x 16 x 4
    mma_gemm<2><<<gattn, blk, SMEM_BYTES>>>(qhi, khi, s, nullptr, inv_scale);

    softmax_kernel<<<BATCH * SEQ, 256>>>(s, phi);

    mma_gemm<3><<<gattn, blk, SMEM_BYTES>>>(phi, vthi, out, nullptr, 0.f);
}

// round 13
// speedup vs baseline: 6.2414x; 1.0638x over previous
#include <cuda_runtime.h>
#include <cuda_fp16.h>
#include <math.h>
#include <stdint.h>

#define SEQ   2048
#define EMB   2048
#define DIM   2048
#define BATCH 4

typedef __half h16;

// ---------------------------------------------------------------------------
// Device scratch (no cudaMalloc allowed anywhere)
// ---------------------------------------------------------------------------
__device__ h16 g_xhi[(size_t)BATCH * SEQ * EMB];
__device__ h16 g_Wqhi[(size_t)DIM * EMB];
__device__ h16 g_Wkhi[(size_t)DIM * EMB];
__device__ h16 g_Wvhi[(size_t)DIM * EMB];
__device__ h16 g_Qhi[(size_t)BATCH * SEQ * DIM];
__device__ h16 g_Khi[(size_t)BATCH * SEQ * DIM];
__device__ h16 g_Vthi[(size_t)BATCH * DIM * SEQ];   // V^T per batch
__device__ float g_S [(size_t)BATCH * SEQ * SEQ];
__device__ h16 g_Phi[(size_t)BATCH * SEQ * SEQ];

// ---------------------------------------------------------------------------
// PTX helpers (sm_80-level PTX only; no arch-suffixed instructions)
// ---------------------------------------------------------------------------
__device__ __forceinline__ uint32_t smem_u32(const void* p) {
    uint32_t a;
    asm("{ .reg .u64 t; cvta.to.shared.u64 t, %1; cvt.u32.u64 %0, t; }"
        : "=r"(a) : "l"(p));
    return a;
}

__device__ __forceinline__ void cp16(uint32_t dst, const void* src) {
    asm volatile("cp.async.cg.shared.global [%0], [%1], 16;" :: "r"(dst), "l"(src));
}
__device__ __forceinline__ void cp_commit() {
    asm volatile("cp.async.commit_group;" ::: "memory");
}
template<int N> __device__ __forceinline__ void cp_wait() {
    asm volatile("cp.async.wait_group %0;" :: "n"(N) : "memory");
}

__device__ __forceinline__ void ldm4(uint32_t& r0, uint32_t& r1, uint32_t& r2,
                                     uint32_t& r3, uint32_t addr) {
    asm volatile("ldmatrix.sync.aligned.m8n8.x4.shared.b16 {%0,%1,%2,%3}, [%4];"
                 : "=r"(r0), "=r"(r1), "=r"(r2), "=r"(r3) : "r"(addr));
}

__device__ __forceinline__ void mma16816(float* c, const uint32_t* a,
                                         uint32_t b0, uint32_t b1) {
    asm volatile(
        "mma.sync.aligned.m16n8k16.row.col.f32.f16.f16.f32 "
        "{%0,%1,%2,%3}, {%4,%5,%6,%7}, {%8,%9}, {%0,%1,%2,%3};"
        : "+f"(c[0]), "+f"(c[1]), "+f"(c[2]), "+f"(c[3])
        : "r"(a[0]), "r"(a[1]), "r"(a[2]), "r"(a[3]), "r"(b0), "r"(b1));
}

// ---------------------------------------------------------------------------
// Tiling constants
// ---------------------------------------------------------------------------
#define ROWB 80                     // smem row stride bytes (32 h16 = 64B data + 16B pad)
#define TILEB (128 * ROWB)          // 10240 B per 128x32 tile
#define STG   (2 * TILEB)           // A, B per stage (1-pass fp16)
static constexpr unsigned SMEM_BYTES = 2 * STG;   // 40960; >= 34816 mode-1 epilogue stage

// ---------------------------------------------------------------------------
// Shared GEMM mainloop (C = A @ B^T, K-major ld 2048), accumulator in-place.
// ---------------------------------------------------------------------------
__device__ __forceinline__ void gemm_mainloop(
    const h16* __restrict__ Ah, const h16* __restrict__ Bh,
    uint32_t sbase, int nk, int tid, int lane, int warp_m, int warp_n,
    float acc[2][8][4])
{
    const int lrow = tid >> 2;
    const int lcb  = (tid & 3) * 16;

    auto load_stage = [&](int kc) {
        const uint32_t sd = sbase + (kc & 1) * STG;
        const size_t goff = (size_t)kc * 32;
        const char* pa = (const char*)(Ah + goff);
        const char* pb = (const char*)(Bh + goff);
#pragma unroll
        for (int i = 0; i < 2; ++i) {
            const int r = lrow + i * 64;
            const uint32_t so = (uint32_t)r * ROWB + lcb;
            const size_t go = (size_t)r * 4096 + lcb;
            cp16(sd + so,         pa + go);
            cp16(sd + TILEB + so, pb + go);
        }
        cp_commit();
    };

    load_stage(0);

    for (int s = 0; s < nk; ++s) {
        if (s + 1 < nk) { load_stage(s + 1); cp_wait<1>(); }
        else            { cp_wait<0>(); }
        __syncthreads();

        const uint32_t sd = sbase + (s & 1) * STG;
        const uint32_t lrh = (uint32_t)(lane & 15) * ROWB + (uint32_t)(lane >> 4) * 16;

#pragma unroll
        for (int half = 0; half < 2; ++half) {
            const uint32_t hb = lrh + (uint32_t)half * 32;

            uint32_t ah[2][4], bh[4][4];
#pragma unroll
            for (int mt = 0; mt < 2; ++mt) {
                const uint32_t ro = (uint32_t)(warp_m * 32 + mt * 16) * ROWB + hb;
                ldm4(ah[mt][0], ah[mt][1], ah[mt][2], ah[mt][3], sd + ro);
            }
#pragma unroll
            for (int g = 0; g < 4; ++g) {
                const uint32_t ro = (uint32_t)(warp_n * 64 + g * 16) * ROWB + hb;
                ldm4(bh[g][0], bh[g][1], bh[g][2], bh[g][3], sd + TILEB + ro);
            }

#pragma unroll
            for (int mt = 0; mt < 2; ++mt)
#pragma unroll
                for (int nt = 0; nt < 8; ++nt) {
                    const int g = nt >> 1, o = nt & 1;
                    mma16816(acc[mt][nt], ah[mt], bh[g][o], bh[g][2 + o]);
                }
        }
        __syncthreads();
    }
}

// ---------------------------------------------------------------------------
// Merged QKV projection kernel. grid (16, 64, 3): z selects W / output / mode.
//   z=0: Q row-major, z=1: K row-major, z=2: V transposed (smem-staged)
// ---------------------------------------------------------------------------
__global__ __launch_bounds__(256, 2)
void proj_gemm(const h16* __restrict__ x,
               const h16* __restrict__ wq, const h16* __restrict__ wk,
               const h16* __restrict__ wv,
               h16* __restrict__ qo, h16* __restrict__ ko, h16* __restrict__ vto)
{
    const int bx = blockIdx.x, by = blockIdx.y, z = blockIdx.z;

    extern __shared__ char smem[];
    const uint32_t sbase = smem_u32(smem);

    const int tid    = threadIdx.x;
    const int wid    = tid >> 5;
    const int lane   = tid & 31;
    const int warp_m = wid & 3;
    const int warp_n = wid >> 2;

    const h16* Bw = (z == 0) ? wq : (z == 1) ? wk : wv;
    h16* out = (z == 0) ? qo : (z == 1) ? ko : vto;

    const h16* Ah = x  + (size_t)(by * 128) * 2048;
    const h16* Bh = Bw + (size_t)(bx * 128) * 2048;

    float acc[2][8][4] = {};
    gemm_mainloop(Ah, Bh, sbase, 64, tid, lane, warp_m, warp_n, acc);

    const int tq = lane >> 2;
    const int tr = lane & 3;

    if (z == 2) {
        // stage tile in smem, coalesced transposed write (V^T)
#pragma unroll
        for (int mt = 0; mt < 2; ++mt)
#pragma unroll
            for (int nt = 0; nt < 8; ++nt) {
                const int ml = warp_m * 32 + mt * 16 + tq;
                const int nl = warp_n * 64 + nt * 8 + tr * 2;
#pragma unroll
                for (int h = 0; h < 2; ++h) {
                    const float c0 = acc[mt][nt][h * 2 + 0];
                    const float c1 = acc[mt][nt][h * 2 + 1];
                    const uint32_t so = (uint32_t)(ml + h * 8) * 272 + (uint32_t)nl * 2;
                    *(__half2*)(smem + so) =
                        __halves2half2(__float2half_rn(c0), __float2half_rn(c1));
                }
            }
        __syncthreads();
        const int b   = by >> 4;
        const int st0 = (by & 15) * 128;
        const int nl  = tid >> 1;
        const int hh  = tid & 1;
        const size_t obase = ((size_t)b * 2048 + bx * 128 + nl) * 2048 + st0 + hh * 64;
#pragma unroll 4
        for (int j = 0; j < 64; j += 2) {
            const uint32_t s0 = (uint32_t)(hh * 64 + j) * 272 + (uint32_t)nl * 2;
            h16 a0 = *(const h16*)(smem + s0);
            h16 a1 = *(const h16*)(smem + s0 + 272);
            *(__half2*)(out + obase + j) = __halves2half2(a0, a1);
        }
        return;
    }

#pragma unroll
    for (int mt = 0; mt < 2; ++mt)
#pragma unroll
        for (int nt = 0; nt < 8; ++nt) {
            const int gm = by * 128 + warp_m * 32 + mt * 16 + tq;
            const int gn = bx * 128 + warp_n * 64 + nt * 8 + tr * 2;
#pragma unroll
            for (int h = 0; h < 2; ++h) {
                const size_t o = (size_t)(gm + h * 8) * 2048 + gn;
                *(__half2*)(out + o) = __halves2half2(
                    __float2half_rn(acc[mt][nt][h * 2 + 0]),
                    __float2half_rn(acc[mt][nt][h * 2 + 1]));
            }
        }
}

// ---------------------------------------------------------------------------
// Attention GEMMs. Heavy-first remap: by = 15 - blockIdx.y.
//   MODE 2: scores -> fp32 * scale, causal tile skip
//   MODE 3: attn @ V^T -> fp32, causal K bound
// ---------------------------------------------------------------------------
template<int MODE>
__global__ __launch_bounds__(256, 2)
void attn_gemm(const h16* __restrict__ Ahi, const h16* __restrict__ Bhi,
               float* __restrict__ out_f, float scale)
{
    const int bx = blockIdx.x;
    const int by = (int)(gridDim.y - 1 - blockIdx.y);   // heavy tiles first
    const int bz = blockIdx.z;
    if (MODE == 2 && bx > by) return;

    extern __shared__ char smem[];
    const uint32_t sbase = smem_u32(smem);

    const int tid    = threadIdx.x;
    const int wid    = tid >> 5;
    const int lane   = tid & 31;
    const int warp_m = wid & 3;
    const int warp_n = wid >> 2;

    const size_t boff = (size_t)bz * 2048 * 2048;
    const h16* Ah = Ahi + boff + (size_t)(by * 128) * 2048;
    const h16* Bh = Bhi + boff + (size_t)(bx * 128) * 2048;

    const int nk = (MODE == 3) ? (by + 1) * 4 : 64;

    float acc[2][8][4] = {};
    gemm_mainloop(Ah, Bh, sbase, nk, tid, lane, warp_m, warp_n, acc);

    const int tq = lane >> 2;
    const int tr = lane & 3;
    const float sc = (MODE == 2) ? scale : 1.0f;

#pragma unroll
    for (int mt = 0; mt < 2; ++mt)
#pragma unroll
        for (int nt = 0; nt < 8; ++nt) {
            const int gm = by * 128 + warp_m * 32 + mt * 16 + tq;
            const int gn = bx * 128 + warp_n * 64 + nt * 8 + tr * 2;
#pragma unroll
            for (int h = 0; h < 2; ++h) {
                const size_t o = boff + (size_t)(gm + h * 8) * 2048 + gn;
                *(float2*)(out_f + o) = make_float2(acc[mt][nt][h * 2 + 0] * sc,
                                                    acc[mt][nt][h * 2 + 1] * sc);
            }
        }
}

// ---------------------------------------------------------------------------
// fp32 -> fp16 rounding, 8 elems/thread (vectorized). n must be multiple of 8.
// ---------------------------------------------------------------------------
__global__ void split8_kernel(const float* __restrict__ s,
                              h16* __restrict__ d, int n)
{
    const int i = (blockIdx.x * blockDim.x + threadIdx.x) * 8;
    if (i >= n) return;
    const float4 a = *(const float4*)(s + i);
    const float4 b = *(const float4*)(s + i + 4);
    __half2 h0 = __floats2half2_rn(a.x, a.y);
    __half2 h1 = __floats2half2_rn(a.z, a.w);
    __half2 h2 = __floats2half2_rn(b.x, b.y);
    __half2 h3 = __floats2half2_rn(b.z, b.w);
    uint4 o;
    o.x = *(uint32_t*)&h0; o.y = *(uint32_t*)&h1;
    o.z = *(uint32_t*)&h2; o.w = *(uint32_t*)&h3;
    *(uint4*)(d + i) = o;
}

// ---------------------------------------------------------------------------
// Causal softmax: fp32 scores (k<=q valid) -> attn fp16.
// Row cached in smem; vectorized global loads (float4) and stores (uint4).
// Writes only k < klim (128-aligned bound); AV never reads beyond.
// ---------------------------------------------------------------------------
__global__ void softmax_kernel(const float* __restrict__ S,
                               h16* __restrict__ Phi)
{
    const int row = blockIdx.x;
    const int b = row >> 11;
    const int q = row & 2047;
    const float* sr = S + ((size_t)b * SEQ + q) * SEQ;
    const size_t ob = ((size_t)b * SEQ + q) * SEQ;
    const int len  = q + 1;
    const int klim = ((q >> 7) + 1) << 7;

    __shared__ float buf[SEQ];
    __shared__ float red[8];

    // pass 1: vectorized load into smem, running max
    float m = -1e30f;
    const int len4 = len & ~3;
    for (int k = threadIdx.x * 4; k < len4; k += blockDim.x * 4) {
        const float4 v = *(const float4*)(sr + k);
        *(float4*)(buf + k) = v;
        m = fmaxf(m, fmaxf(fmaxf(v.x, v.y), fmaxf(v.z, v.w)));
    }
    for (int k = len4 + threadIdx.x; k < len; k += blockDim.x) {
        const float v = sr[k];
        buf[k] = v;
        m = fmaxf(m, v);
    }
#pragma unroll
    for (int o = 16; o; o >>= 1)
        m = fmaxf(m, __shfl_xor_sync(0xffffffffu, m, o));
    if ((threadIdx.x & 31) == 0) red[threadIdx.x >> 5] = m;
    __syncthreads();
    m = red[0];
#pragma unroll
    for (int w = 1; w < 8; ++w) m = fmaxf(m, red[w]);

    // pass 2: exp in smem, running sum
    float sum = 0.f;
    for (int k = threadIdx.x; k < len; k += blockDim.x) {
        const float e = __expf(buf[k] - m);
        buf[k] = e;
        sum += e;
    }
#pragma unroll
    for (int o = 16; o; o >>= 1)
        sum += __shfl_xor_sync(0xffffffffu, sum, o);
    __syncthreads();
    if ((threadIdx.x & 31) == 0) red[threadIdx.x >> 5] = sum;
    __syncthreads();
    sum = 0.f;
#pragma unroll
    for (int w = 0; w < 8; ++w) sum += red[w];

    const float inv = 1.0f / sum;

    // pass 3: normalized fp16 writes, 8 per thread (klim multiple of 128)
    for (int k = threadIdx.x * 8; k < klim; k += blockDim.x * 8) {
        __half2 h[4];
#pragma unroll
        for (int j = 0; j < 4; ++j) {
            const int k0 = k + j * 2;
            const float a0 = (k0     < len) ? buf[k0]     * inv : 0.f;
            const float a1 = (k0 + 1 < len) ? buf[k0 + 1] * inv : 0.f;
            h[j] = __floats2half2_rn(a0, a1);
        }
        uint4 o;
        o.x = *(uint32_t*)&h[0]; o.y = *(uint32_t*)&h[1];
        o.z = *(uint32_t*)&h[2]; o.w = *(uint32_t*)&h[3];
        *(uint4*)(Phi + ob + k) = o;
    }
}

// ---------------------------------------------------------------------------
extern "C" void kernel_launch(void* const* d_in, const int* in_sizes, int n_in,
                              void* d_out, int out_size)
{
    const float* x  = (const float*)d_in[0];
    const float* Wk = (const float*)d_in[1];
    const float* Wq = (const float*)d_in[2];
    const float* Wv = (const float*)d_in[3];
    float* out = (float*)d_out;

    h16 *xhi, *wqh, *wkh, *wvh;
    h16 *qhi, *khi, *vthi, *phi;
    float* s;
    cudaGetSymbolAddress((void**)&xhi,  g_xhi);
    cudaGetSymbolAddress((void**)&wqh,  g_Wqhi);
    cudaGetSymbolAddress((void**)&wkh,  g_Wkhi);
    cudaGetSymbolAddress((void**)&wvh,  g_Wvhi);
    cudaGetSymbolAddress((void**)&qhi,  g_Qhi);
    cudaGetSymbolAddress((void**)&khi,  g_Khi);
    cudaGetSymbolAddress((void**)&vthi, g_Vthi);
    cudaGetSymbolAddress((void**)&phi,  g_Phi);
    cudaGetSymbolAddress((void**)&s,    g_S);

    cudaFuncSetAttribute((const void*)proj_gemm,    cudaFuncAttributeMaxDynamicSharedMemorySize, SMEM_BYTES);
    cudaFuncSetAttribute((const void*)attn_gemm<2>, cudaFuncAttributeMaxDynamicSharedMemorySize, SMEM_BYTES);
    cudaFuncSetAttribute((const void*)attn_gemm<3>, cudaFuncAttributeMaxDynamicSharedMemorySize, SMEM_BYTES);

    const float inv_scale = 1.0f / sqrtf((float)DIM);

    {
        int n = BATCH * SEQ * EMB;              // 16,777,216
        split8_kernel<<<(n / 8 + 255) / 256, 256>>>(x, xhi, n);
        int nw = DIM * EMB;                     // 4,194,304
        split8_kernel<<<(nw / 8 + 255) / 256, 256>>>(Wq, wqh, nw);
        split8_kernel<<<(nw / 8 + 255) / 256, 256>>>(Wk, wkh, nw);
        split8_kernel<<<(nw / 8 + 255) / 256, 256>>>(Wv, wvh, nw);
    }

    dim3 blk(256);
    dim3 gproj(DIM / 128, (BATCH * SEQ) / 128, 3);      // 16 x 64 x 3
    proj_gemm<<<gproj, blk, SMEM_BYTES>>>(xhi, wqh, wkh, wvh, qhi, khi, vthi);

    dim3 gattn(SEQ / 128, SEQ / 128, BATCH);            // 16 x 16 x 4
    attn_gemm<2><<<gattn, blk, SMEM_BYTES>>>(qhi, khi, s, inv_scale);

    softmax_kernel<<<BATCH * SEQ, 256>>>(s, phi);

    attn_gemm<3><<<gattn, blk, SMEM_BYTES>>>(phi, vthi, out, 0.f);
}

// round 14
// speedup vs baseline: 6.5373x; 1.0474x over previous
#include <cuda_runtime.h>
#include <cuda_fp16.h>
#include <math.h>
#include <stdint.h>

#define SEQ   2048
#define EMB   2048
#define DIM   2048
#define BATCH 4

typedef __half h16;

// ---------------------------------------------------------------------------
// Device scratch (no cudaMalloc allowed anywhere)
// ---------------------------------------------------------------------------
__device__ h16 g_xhi[(size_t)BATCH * SEQ * EMB];
__device__ h16 g_Wqhi[(size_t)DIM * EMB];
__device__ h16 g_Wkhi[(size_t)DIM * EMB];
__device__ h16 g_Wvhi[(size_t)DIM * EMB];
__device__ h16 g_Qhi[(size_t)BATCH * SEQ * DIM];
__device__ h16 g_Khi[(size_t)BATCH * SEQ * DIM];
__device__ h16 g_Vthi[(size_t)BATCH * DIM * SEQ];   // V^T per batch
__device__ float g_S [(size_t)BATCH * SEQ * SEQ];
__device__ h16 g_Phi[(size_t)BATCH * SEQ * SEQ];

// ---------------------------------------------------------------------------
// PTX helpers (sm_80-level PTX only; no arch-suffixed instructions)
// ---------------------------------------------------------------------------
__device__ __forceinline__ uint32_t smem_u32(const void* p) {
    uint32_t a;
    asm("{ .reg .u64 t; cvta.to.shared.u64 t, %1; cvt.u32.u64 %0, t; }"
        : "=r"(a) : "l"(p));
    return a;
}

__device__ __forceinline__ void cp16(uint32_t dst, const void* src) {
    asm volatile("cp.async.cg.shared.global [%0], [%1], 16;" :: "r"(dst), "l"(src));
}
__device__ __forceinline__ void cp_commit() {
    asm volatile("cp.async.commit_group;" ::: "memory");
}
template<int N> __device__ __forceinline__ void cp_wait() {
    asm volatile("cp.async.wait_group %0;" :: "n"(N) : "memory");
}

__device__ __forceinline__ void ldm4(uint32_t& r0, uint32_t& r1, uint32_t& r2,
                                     uint32_t& r3, uint32_t addr) {
    asm volatile("ldmatrix.sync.aligned.m8n8.x4.shared.b16 {%0,%1,%2,%3}, [%4];"
                 : "=r"(r0), "=r"(r1), "=r"(r2), "=r"(r3) : "r"(addr));
}

__device__ __forceinline__ void mma16816(float* c, const uint32_t* a,
                                         uint32_t b0, uint32_t b1) {
    asm volatile(
        "mma.sync.aligned.m16n8k16.row.col.f32.f16.f16.f32 "
        "{%0,%1,%2,%3}, {%4,%5,%6,%7}, {%8,%9}, {%0,%1,%2,%3};"
        : "+f"(c[0]), "+f"(c[1]), "+f"(c[2]), "+f"(c[3])
        : "r"(a[0]), "r"(a[1]), "r"(a[2]), "r"(a[3]), "r"(b0), "r"(b1));
}

// ---------------------------------------------------------------------------
// Tiling constants
// ---------------------------------------------------------------------------
#define ROWB 80                     // smem row stride bytes (32 h16 = 64B data + 16B pad)
#define TILEB (128 * ROWB)          // 10240 B per 128x32 tile
#define STG   (2 * TILEB)           // A, B per stage (1-pass fp16)
#define NSTAGE 5                    // ring depth (single-barrier-per-chunk safe)
static constexpr unsigned SMEM_BYTES = NSTAGE * STG;   // 102400; >= 34816 epilogue stage

// ---------------------------------------------------------------------------
// Shared GEMM mainloop (C = A @ B^T, K-major ld 2048).
// 5-deep cp.async ring, prefetch distance 3, ONE barrier per 32-K chunk.
// Safety: per-thread order [load s+3 | cp_wait<3> | BAR | consume s]; the
// iter-s barrier fences consume(s-1) for all threads, and the only slot a
// later load overwrites is (s-1)%5.
// ---------------------------------------------------------------------------
__device__ __forceinline__ void gemm_mainloop(
    const h16* __restrict__ Ah, const h16* __restrict__ Bh,
    uint32_t sbase, int nk, int tid, int lane, int warp_m, int warp_n,
    float acc[2][8][4])
{
    const int lrow = tid >> 2;
    const int lcb  = (tid & 3) * 16;

    auto load_stage = [&](int kc) {
        const uint32_t sd = sbase + (uint32_t)(kc % NSTAGE) * STG;
        const size_t goff = (size_t)kc * 32;
        const char* pa = (const char*)(Ah + goff);
        const char* pb = (const char*)(Bh + goff);
#pragma unroll
        for (int i = 0; i < 2; ++i) {
            const int r = lrow + i * 64;
            const uint32_t so = (uint32_t)r * ROWB + lcb;
            const size_t go = (size_t)r * 4096 + lcb;
            cp16(sd + so,         pa + go);
            cp16(sd + TILEB + so, pb + go);
        }
        cp_commit();
    };

    load_stage(0);
    load_stage(1);
    load_stage(2);

    for (int s = 0; s < nk; ++s) {
        if (s + 3 < nk) load_stage(s + 3);
        else            cp_commit();          // empty group keeps wait count aligned
        cp_wait<3>();                          // own stage-s loads complete
        __syncthreads();                       // everyone's stage-s loads complete

        const uint32_t sd = sbase + (uint32_t)(s % NSTAGE) * STG;
        const uint32_t lrh = (uint32_t)(lane & 15) * ROWB + (uint32_t)(lane >> 4) * 16;

#pragma unroll
        for (int half = 0; half < 2; ++half) {
            const uint32_t hb = lrh + (uint32_t)half * 32;

            uint32_t ah[2][4], bh[4][4];
#pragma unroll
            for (int mt = 0; mt < 2; ++mt) {
                const uint32_t ro = (uint32_t)(warp_m * 32 + mt * 16) * ROWB + hb;
                ldm4(ah[mt][0], ah[mt][1], ah[mt][2], ah[mt][3], sd + ro);
            }
#pragma unroll
            for (int g = 0; g < 4; ++g) {
                const uint32_t ro = (uint32_t)(warp_n * 64 + g * 16) * ROWB + hb;
                ldm4(bh[g][0], bh[g][1], bh[g][2], bh[g][3], sd + TILEB + ro);
            }

#pragma unroll
            for (int mt = 0; mt < 2; ++mt)
#pragma unroll
                for (int nt = 0; nt < 8; ++nt) {
                    const int g = nt >> 1, o = nt & 1;
                    mma16816(acc[mt][nt], ah[mt], bh[g][o], bh[g][2 + o]);
                }
        }
        // no trailing barrier: next iter's load only touches slot (s-1)%5
    }
    __syncthreads();   // protect smem reuse by epilogue staging
}

// ---------------------------------------------------------------------------
// Merged QKV projection kernel. grid (16, 64, 3): z selects W / output / mode.
//   z=0: Q row-major, z=1: K row-major, z=2: V transposed (smem-staged)
// ---------------------------------------------------------------------------
__global__ __launch_bounds__(256, 2)
void proj_gemm(const h16* __restrict__ x,
               const h16* __restrict__ wq, const h16* __restrict__ wk,
               const h16* __restrict__ wv,
               h16* __restrict__ qo, h16* __restrict__ ko, h16* __restrict__ vto)
{
    const int bx = blockIdx.x, by = blockIdx.y, z = blockIdx.z;

    extern __shared__ char smem[];
    const uint32_t sbase = smem_u32(smem);

    const int tid    = threadIdx.x;
    const int wid    = tid >> 5;
    const int lane   = tid & 31;
    const int warp_m = wid & 3;
    const int warp_n = wid >> 2;

    const h16* Bw = (z == 0) ? wq : (z == 1) ? wk : wv;
    h16* out = (z == 0) ? qo : (z == 1) ? ko : vto;

    const h16* Ah = x  + (size_t)(by * 128) * 2048;
    const h16* Bh = Bw + (size_t)(bx * 128) * 2048;

    float acc[2][8][4] = {};
    gemm_mainloop(Ah, Bh, sbase, 64, tid, lane, warp_m, warp_n, acc);

    const int tq = lane >> 2;
    const int tr = lane & 3;

    if (z == 2) {
        // stage tile in smem, coalesced transposed write (V^T)
#pragma unroll
        for (int mt = 0; mt < 2; ++mt)
#pragma unroll
            for (int nt = 0; nt < 8; ++nt) {
                const int ml = warp_m * 32 + mt * 16 + tq;
                const int nl = warp_n * 64 + nt * 8 + tr * 2;
#pragma unroll
                for (int h = 0; h < 2; ++h) {
                    const float c0 = acc[mt][nt][h * 2 + 0];
                    const float c1 = acc[mt][nt][h * 2 + 1];
                    const uint32_t so = (uint32_t)(ml + h * 8) * 272 + (uint32_t)nl * 2;
                    *(__half2*)(smem + so) =
                        __halves2half2(__float2half_rn(c0), __float2half_rn(c1));
                }
            }
        __syncthreads();
        const int b   = by >> 4;
        const int st0 = (by & 15) * 128;
        const int nl  = tid >> 1;
        const int hh  = tid & 1;
        const size_t obase = ((size_t)b * 2048 + bx * 128 + nl) * 2048 + st0 + hh * 64;
#pragma unroll 4
        for (int j = 0; j < 64; j += 2) {
            const uint32_t s0 = (uint32_t)(hh * 64 + j) * 272 + (uint32_t)nl * 2;
            h16 a0 = *(const h16*)(smem + s0);
            h16 a1 = *(const h16*)(smem + s0 + 272);
            *(__half2*)(out + obase + j) = __halves2half2(a0, a1);
        }
        return;
    }

#pragma unroll
    for (int mt = 0; mt < 2; ++mt)
#pragma unroll
        for (int nt = 0; nt < 8; ++nt) {
            const int gm = by * 128 + warp_m * 32 + mt * 16 + tq;
            const int gn = bx * 128 + warp_n * 64 + nt * 8 + tr * 2;
#pragma unroll
            for (int h = 0; h < 2; ++h) {
                const size_t o = (size_t)(gm + h * 8) * 2048 + gn;
                *(__half2*)(out + o) = __halves2half2(
                    __float2half_rn(acc[mt][nt][h * 2 + 0]),
                    __float2half_rn(acc[mt][nt][h * 2 + 1]));
            }
        }
}

// ---------------------------------------------------------------------------
// Attention GEMMs. Heavy-first remap: by = 15 - blockIdx.y.
//   MODE 2: scores -> fp32 * scale, causal tile skip
//   MODE 3: attn @ V^T -> fp32, causal K bound
// ---------------------------------------------------------------------------
template<int MODE>
__global__ __launch_bounds__(256, 2)
void attn_gemm(const h16* __restrict__ Ahi, const h16* __restrict__ Bhi,
               float* __restrict__ out_f, float scale)
{
    const int bx = blockIdx.x;
    const int by = (int)(gridDim.y - 1 - blockIdx.y);   // heavy tiles first
    const int bz = blockIdx.z;
    if (MODE == 2 && bx > by) return;

    extern __shared__ char smem[];
    const uint32_t sbase = smem_u32(smem);

    const int tid    = threadIdx.x;
    const int wid    = tid >> 5;
    const int lane   = tid & 31;
    const int warp_m = wid & 3;
    const int warp_n = wid >> 2;

    const size_t boff = (size_t)bz * 2048 * 2048;
    const h16* Ah = Ahi + boff + (size_t)(by * 128) * 2048;
    const h16* Bh = Bhi + boff + (size_t)(bx * 128) * 2048;

    const int nk = (MODE == 3) ? (by + 1) * 4 : 64;

    float acc[2][8][4] = {};
    gemm_mainloop(Ah, Bh, sbase, nk, tid, lane, warp_m, warp_n, acc);

    const int tq = lane >> 2;
    const int tr = lane & 3;
    const float sc = (MODE == 2) ? scale : 1.0f;

#pragma unroll
    for (int mt = 0; mt < 2; ++mt)
#pragma unroll
        for (int nt = 0; nt < 8; ++nt) {
            const int gm = by * 128 + warp_m * 32 + mt * 16 + tq;
            const int gn = bx * 128 + warp_n * 64 + nt * 8 + tr * 2;
#pragma unroll
            for (int h = 0; h < 2; ++h) {
                const size_t o = boff + (size_t)(gm + h * 8) * 2048 + gn;
                *(float2*)(out_f + o) = make_float2(acc[mt][nt][h * 2 + 0] * sc,
                                                    acc[mt][nt][h * 2 + 1] * sc);
            }
        }
}

// ---------------------------------------------------------------------------
// Merged fp32 -> fp16 rounding for all 4 inputs. grid.y selects the tensor.
// 8 elems/thread; sizes are multiples of 8.
// ---------------------------------------------------------------------------
__global__ void split_all_kernel(const float* __restrict__ x,
                                 const float* __restrict__ wq,
                                 const float* __restrict__ wk,
                                 const float* __restrict__ wv,
                                 h16* __restrict__ xo, h16* __restrict__ qo,
                                 h16* __restrict__ ko, h16* __restrict__ vo)
{
    const int a = blockIdx.y;
    const float* s = (a == 0) ? x : (a == 1) ? wq : (a == 2) ? wk : wv;
    h16* d        = (a == 0) ? xo : (a == 1) ? qo : (a == 2) ? ko : vo;
    const int n   = (a == 0) ? BATCH * SEQ * EMB : DIM * EMB;

    const int i = (blockIdx.x * blockDim.x + threadIdx.x) * 8;
    if (i >= n) return;
    const float4 p = *(const float4*)(s + i);
    const float4 q = *(const float4*)(s + i + 4);
    __half2 h0 = __floats2half2_rn(p.x, p.y);
    __half2 h1 = __floats2half2_rn(p.z, p.w);
    __half2 h2 = __floats2half2_rn(q.x, q.y);
    __half2 h3 = __floats2half2_rn(q.z, q.w);
    uint4 o;
    o.x = *(uint32_t*)&h0; o.y = *(uint32_t*)&h1;
    o.z = *(uint32_t*)&h2; o.w = *(uint32_t*)&h3;
    *(uint4*)(d + i) = o;
}

// ---------------------------------------------------------------------------
// Causal softmax: fp32 scores (k<=q valid) -> attn fp16. Longest rows first.
// Row cached in smem; vectorized loads/stores. Writes only k < klim.
// ---------------------------------------------------------------------------
__global__ void softmax_kernel(const float* __restrict__ S,
                               h16* __restrict__ Phi)
{
    const int row = (int)(gridDim.x - 1 - blockIdx.x);   // heavy rows first
    const int b = row >> 11;
    const int q = row & 2047;
    const float* sr = S + ((size_t)b * SEQ + q) * SEQ;
    const size_t ob = ((size_t)b * SEQ + q) * SEQ;
    const int len  = q + 1;
    const int klim = ((q >> 7) + 1) << 7;

    __shared__ float buf[SEQ];
    __shared__ float red[8];

    float m = -1e30f;
    const int len4 = len & ~3;
    for (int k = threadIdx.x * 4; k < len4; k += blockDim.x * 4) {
        const float4 v = *(const float4*)(sr + k);
        *(float4*)(buf + k) = v;
        m = fmaxf(m, fmaxf(fmaxf(v.x, v.y), fmaxf(v.z, v.w)));
    }
    for (int k = len4 + threadIdx.x; k < len; k += blockDim.x) {
        const float v = sr[k];
        buf[k] = v;
        m = fmaxf(m, v);
    }
#pragma unroll
    for (int o = 16; o; o >>= 1)
        m = fmaxf(m, __shfl_xor_sync(0xffffffffu, m, o));
    if ((threadIdx.x & 31) == 0) red[threadIdx.x >> 5] = m;
    __syncthreads();
    m = red[0];
#pragma unroll
    for (int w = 1; w < 8; ++w) m = fmaxf(m, red[w]);

    float sum = 0.f;
    for (int k = threadIdx.x; k < len; k += blockDim.x) {
        const float e = __expf(buf[k] - m);
        buf[k] = e;
        sum += e;
    }
#pragma unroll
    for (int o = 16; o; o >>= 1)
        sum += __shfl_xor_sync(0xffffffffu, sum, o);
    __syncthreads();
    if ((threadIdx.x & 31) == 0) red[threadIdx.x >> 5] = sum;
    __syncthreads();
    sum = 0.f;
#pragma unroll
    for (int w = 0; w < 8; ++w) sum += red[w];

    const float inv = 1.0f / sum;

    for (int k = threadIdx.x * 8; k < klim; k += blockDim.x * 8) {
        __half2 h[4];
#pragma unroll
        for (int j = 0; j < 4; ++j) {
            const int k0 = k + j * 2;
            const float a0 = (k0     < len) ? buf[k0]     * inv : 0.f;
            const float a1 = (k0 + 1 < len) ? buf[k0 + 1] * inv : 0.f;
            h[j] = __floats2half2_rn(a0, a1);
        }
        uint4 o;
        o.x = *(uint32_t*)&h[0]; o.y = *(uint32_t*)&h[1];
        o.z = *(uint32_t*)&h[2]; o.w = *(uint32_t*)&h[3];
        *(uint4*)(Phi + ob + k) = o;
    }
}

// ---------------------------------------------------------------------------
extern "C" void kernel_launch(void* const* d_in, const int* in_sizes, int n_in,
                              void* d_out, int out_size)
{
    const float* x  = (const float*)d_in[0];
    const float* Wk = (const float*)d_in[1];
    const float* Wq = (const float*)d_in[2];
    const float* Wv = (const float*)d_in[3];
    float* out = (float*)d_out;

    h16 *xhi, *wqh, *wkh, *wvh;
    h16 *qhi, *khi, *vthi, *phi;
    float* s;
    cudaGetSymbolAddress((void**)&xhi,  g_xhi);
    cudaGetSymbolAddress((void**)&wqh,  g_Wqhi);
    cudaGetSymbolAddress((void**)&wkh,  g_Wkhi);
    cudaGetSymbolAddress((void**)&wvh,  g_Wvhi);
    cudaGetSymbolAddress((void**)&qhi,  g_Qhi);
    cudaGetSymbolAddress((void**)&khi,  g_Khi);
    cudaGetSymbolAddress((void**)&vthi, g_Vthi);
    cudaGetSymbolAddress((void**)&phi,  g_Phi);
    cudaGetSymbolAddress((void**)&s,    g_S);

    cudaFuncSetAttribute((const void*)proj_gemm,    cudaFuncAttributeMaxDynamicSharedMemorySize, SMEM_BYTES);
    cudaFuncSetAttribute((const void*)attn_gemm<2>, cudaFuncAttributeMaxDynamicSharedMemorySize, SMEM_BYTES);
    cudaFuncSetAttribute((const void*)attn_gemm<3>, cudaFuncAttributeMaxDynamicSharedMemorySize, SMEM_BYTES);

    const float inv_scale = 1.0f / sqrtf((float)DIM);

    {
        // x: 16.8M elems -> 8192 blocks; W: 4.19M -> 2048 (guarded)
        dim3 gs((BATCH * SEQ * EMB / 8 + 255) / 256, 4);
        split_all_kernel<<<gs, 256>>>(x, Wq, Wk, Wv, xhi, wqh, wkh, wvh);
    }

    dim3 blk(256);
    dim3 gproj(DIM / 128, (BATCH * SEQ) / 128, 3);      // 16 x 64 x 3
    proj_gemm<<<gproj, blk, SMEM_BYTES>>>(xhi, wqh, wkh, wvh, qhi, khi, vthi);

    dim3 gattn(SEQ / 128, SEQ / 128, BATCH);            // 16 x 16 x 4
    attn_gemm<2><<<gattn, blk, SMEM_BYTES>>>(qhi, khi, s, inv_scale);

    softmax_kernel<<<BATCH * SEQ, 256>>>(s, phi);

    attn_gemm<3><<<gattn, blk, SMEM_BYTES>>>(phi, vthi, out, 0.f);
}

// round 15
// speedup vs baseline: 6.5399x; 1.0004x over previous
#include <cuda_runtime.h>
#include <cuda_fp16.h>
#include <math.h>
#include <stdint.h>

#define SEQ   2048
#define EMB   2048
#define DIM   2048
#define BATCH 4

typedef __half h16;

// ---------------------------------------------------------------------------
// Device scratch (no cudaMalloc allowed anywhere)
// ---------------------------------------------------------------------------
__device__ h16 g_xhi[(size_t)BATCH * SEQ * EMB];
__device__ h16 g_Wqhi[(size_t)DIM * EMB];
__device__ h16 g_Wkhi[(size_t)DIM * EMB];
__device__ h16 g_Wvhi[(size_t)DIM * EMB];
__device__ h16 g_Qhi[(size_t)BATCH * SEQ * DIM];
__device__ h16 g_Khi[(size_t)BATCH * SEQ * DIM];
__device__ h16 g_Vthi[(size_t)BATCH * DIM * SEQ];   // V^T per batch
__device__ float g_S [(size_t)BATCH * SEQ * SEQ];
__device__ h16 g_Phi[(size_t)BATCH * SEQ * SEQ];

// ---------------------------------------------------------------------------
// PTX helpers (sm_80-level PTX only; no arch-suffixed instructions)
// ---------------------------------------------------------------------------
__device__ __forceinline__ uint32_t smem_u32(const void* p) {
    uint32_t a;
    asm("{ .reg .u64 t; cvta.to.shared.u64 t, %1; cvt.u32.u64 %0, t; }"
        : "=r"(a) : "l"(p));
    return a;
}

__device__ __forceinline__ void cp16(uint32_t dst, const void* src) {
    asm volatile("cp.async.cg.shared.global [%0], [%1], 16;" :: "r"(dst), "l"(src));
}
__device__ __forceinline__ void cp_commit() {
    asm volatile("cp.async.commit_group;" ::: "memory");
}
template<int N> __device__ __forceinline__ void cp_wait() {
    asm volatile("cp.async.wait_group %0;" :: "n"(N) : "memory");
}

__device__ __forceinline__ void ldm4(uint32_t& r0, uint32_t& r1, uint32_t& r2,
                                     uint32_t& r3, uint32_t addr) {
    asm volatile("ldmatrix.sync.aligned.m8n8.x4.shared.b16 {%0,%1,%2,%3}, [%4];"
                 : "=r"(r0), "=r"(r1), "=r"(r2), "=r"(r3) : "r"(addr));
}

__device__ __forceinline__ void mma16816(float* c, const uint32_t* a,
                                         uint32_t b0, uint32_t b1) {
    asm volatile(
        "mma.sync.aligned.m16n8k16.row.col.f32.f16.f16.f32 "
        "{%0,%1,%2,%3}, {%4,%5,%6,%7}, {%8,%9}, {%0,%1,%2,%3};"
        : "+f"(c[0]), "+f"(c[1]), "+f"(c[2]), "+f"(c[3])
        : "r"(a[0]), "r"(a[1]), "r"(a[2]), "r"(a[3]), "r"(b0), "r"(b1));
}

// ---------------------------------------------------------------------------
// Tiling constants
// ---------------------------------------------------------------------------
#define ROWB 80                     // smem row stride bytes (32 h16 = 64B data + 16B pad)
#define TILEB (128 * ROWB)          // 10240 B per 128x32 tile
#define STG   (2 * TILEB)           // A, B per stage (1-pass fp16)
#define NSTAGE 5                    // ring depth (single-barrier-per-chunk safe)
static constexpr unsigned SMEM_BYTES = NSTAGE * STG;   // 102400; >= 34816 epilogue stage

// ---------------------------------------------------------------------------
// Shared GEMM mainloop (C = A @ B^T, K-major ld 2048).
// 5-deep cp.async ring, prefetch distance 3, ONE barrier per 32-K chunk.
// ---------------------------------------------------------------------------
__device__ __forceinline__ void gemm_mainloop(
    const h16* __restrict__ Ah, const h16* __restrict__ Bh,
    uint32_t sbase, int nk, int tid, int lane, int warp_m, int warp_n,
    float acc[2][8][4])
{
    const int lrow = tid >> 2;
    const int lcb  = (tid & 3) * 16;

    auto load_stage = [&](int kc) {
        const uint32_t sd = sbase + (uint32_t)(kc % NSTAGE) * STG;
        const size_t goff = (size_t)kc * 32;
        const char* pa = (const char*)(Ah + goff);
        const char* pb = (const char*)(Bh + goff);
#pragma unroll
        for (int i = 0; i < 2; ++i) {
            const int r = lrow + i * 64;
            const uint32_t so = (uint32_t)r * ROWB + lcb;
            const size_t go = (size_t)r * 4096 + lcb;
            cp16(sd + so,         pa + go);
            cp16(sd + TILEB + so, pb + go);
        }
        cp_commit();
    };

    load_stage(0);
    load_stage(1);
    load_stage(2);

    for (int s = 0; s < nk; ++s) {
        if (s + 3 < nk) load_stage(s + 3);
        else            cp_commit();          // empty group keeps wait count aligned
        cp_wait<3>();
        __syncthreads();

        const uint32_t sd = sbase + (uint32_t)(s % NSTAGE) * STG;
        const uint32_t lrh = (uint32_t)(lane & 15) * ROWB + (uint32_t)(lane >> 4) * 16;

#pragma unroll
        for (int half = 0; half < 2; ++half) {
            const uint32_t hb = lrh + (uint32_t)half * 32;

            uint32_t ah[2][4], bh[4][4];
#pragma unroll
            for (int mt = 0; mt < 2; ++mt) {
                const uint32_t ro = (uint32_t)(warp_m * 32 + mt * 16) * ROWB + hb;
                ldm4(ah[mt][0], ah[mt][1], ah[mt][2], ah[mt][3], sd + ro);
            }
#pragma unroll
            for (int g = 0; g < 4; ++g) {
                const uint32_t ro = (uint32_t)(warp_n * 64 + g * 16) * ROWB + hb;
                ldm4(bh[g][0], bh[g][1], bh[g][2], bh[g][3], sd + TILEB + ro);
            }

#pragma unroll
            for (int mt = 0; mt < 2; ++mt)
#pragma unroll
                for (int nt = 0; nt < 8; ++nt) {
                    const int g = nt >> 1, o = nt & 1;
                    mma16816(acc[mt][nt], ah[mt], bh[g][o], bh[g][2 + o]);
                }
        }
    }
    __syncthreads();   // protect smem reuse by epilogue staging
}

// ---------------------------------------------------------------------------
// QKV projection kernel. z = blockIdx.z + zbase selects W / output / mode.
//   z=0: Q row-major, z=1: K row-major, z=2: V transposed (smem-staged)
// Launched as grid.z=2 (zbase=0, QK) on the main stream and grid.z=1
// (zbase=2, V) on the side stream.
// ---------------------------------------------------------------------------
__global__ __launch_bounds__(256, 2)
void proj_gemm(const h16* __restrict__ x,
               const h16* __restrict__ wq, const h16* __restrict__ wk,
               const h16* __restrict__ wv,
               h16* __restrict__ qo, h16* __restrict__ ko, h16* __restrict__ vto,
               int zbase)
{
    const int bx = blockIdx.x, by = blockIdx.y;
    const int z  = (int)blockIdx.z + zbase;

    extern __shared__ char smem[];
    const uint32_t sbase = smem_u32(smem);

    const int tid    = threadIdx.x;
    const int wid    = tid >> 5;
    const int lane   = tid & 31;
    const int warp_m = wid & 3;
    const int warp_n = wid >> 2;

    const h16* Bw = (z == 0) ? wq : (z == 1) ? wk : wv;
    h16* out = (z == 0) ? qo : (z == 1) ? ko : vto;

    const h16* Ah = x  + (size_t)(by * 128) * 2048;
    const h16* Bh = Bw + (size_t)(bx * 128) * 2048;

    float acc[2][8][4] = {};
    gemm_mainloop(Ah, Bh, sbase, 64, tid, lane, warp_m, warp_n, acc);

    const int tq = lane >> 2;
    const int tr = lane & 3;

    if (z == 2) {
        // stage tile in smem, coalesced transposed write (V^T)
#pragma unroll
        for (int mt = 0; mt < 2; ++mt)
#pragma unroll
            for (int nt = 0; nt < 8; ++nt) {
                const int ml = warp_m * 32 + mt * 16 + tq;
                const int nl = warp_n * 64 + nt * 8 + tr * 2;
#pragma unroll
                for (int h = 0; h < 2; ++h) {
                    const float c0 = acc[mt][nt][h * 2 + 0];
                    const float c1 = acc[mt][nt][h * 2 + 1];
                    const uint32_t so = (uint32_t)(ml + h * 8) * 272 + (uint32_t)nl * 2;
                    *(__half2*)(smem + so) =
                        __halves2half2(__float2half_rn(c0), __float2half_rn(c1));
                }
            }
        __syncthreads();
        const int b   = by >> 4;
        const int st0 = (by & 15) * 128;
        const int nl  = tid >> 1;
        const int hh  = tid & 1;
        const size_t obase = ((size_t)b * 2048 + bx * 128 + nl) * 2048 + st0 + hh * 64;
#pragma unroll 4
        for (int j = 0; j < 64; j += 2) {
            const uint32_t s0 = (uint32_t)(hh * 64 + j) * 272 + (uint32_t)nl * 2;
            h16 a0 = *(const h16*)(smem + s0);
            h16 a1 = *(const h16*)(smem + s0 + 272);
            *(__half2*)(out + obase + j) = __halves2half2(a0, a1);
        }
        return;
    }

#pragma unroll
    for (int mt = 0; mt < 2; ++mt)
#pragma unroll
        for (int nt = 0; nt < 8; ++nt) {
            const int gm = by * 128 + warp_m * 32 + mt * 16 + tq;
            const int gn = bx * 128 + warp_n * 64 + nt * 8 + tr * 2;
#pragma unroll
            for (int h = 0; h < 2; ++h) {
                const size_t o = (size_t)(gm + h * 8) * 2048 + gn;
                *(__half2*)(out + o) = __halves2half2(
                    __float2half_rn(acc[mt][nt][h * 2 + 0]),
                    __float2half_rn(acc[mt][nt][h * 2 + 1]));
            }
        }
}

// ---------------------------------------------------------------------------
// Attention GEMMs. Heavy-first remap: by = 15 - blockIdx.y.
//   MODE 2: scores -> fp32 * scale, causal tile skip
//   MODE 3: attn @ V^T -> fp32, causal K bound
// ---------------------------------------------------------------------------
template<int MODE>
__global__ __launch_bounds__(256, 2)
void attn_gemm(const h16* __restrict__ Ahi, const h16* __restrict__ Bhi,
               float* __restrict__ out_f, float scale)
{
    const int bx = blockIdx.x;
    const int by = (int)(gridDim.y - 1 - blockIdx.y);   // heavy tiles first
    const int bz = blockIdx.z;
    if (MODE == 2 && bx > by) return;

    extern __shared__ char smem[];
    const uint32_t sbase = smem_u32(smem);

    const int tid    = threadIdx.x;
    const int wid    = tid >> 5;
    const int lane   = tid & 31;
    const int warp_m = wid & 3;
    const int warp_n = wid >> 2;

    const size_t boff = (size_t)bz * 2048 * 2048;
    const h16* Ah = Ahi + boff + (size_t)(by * 128) * 2048;
    const h16* Bh = Bhi + boff + (size_t)(bx * 128) * 2048;

    const int nk = (MODE == 3) ? (by + 1) * 4 : 64;

    float acc[2][8][4] = {};
    gemm_mainloop(Ah, Bh, sbase, nk, tid, lane, warp_m, warp_n, acc);

    const int tq = lane >> 2;
    const int tr = lane & 3;
    const float sc = (MODE == 2) ? scale : 1.0f;

#pragma unroll
    for (int mt = 0; mt < 2; ++mt)
#pragma unroll
        for (int nt = 0; nt < 8; ++nt) {
            const int gm = by * 128 + warp_m * 32 + mt * 16 + tq;
            const int gn = bx * 128 + warp_n * 64 + nt * 8 + tr * 2;
#pragma unroll
            for (int h = 0; h < 2; ++h) {
                const size_t o = boff + (size_t)(gm + h * 8) * 2048 + gn;
                *(float2*)(out_f + o) = make_float2(acc[mt][nt][h * 2 + 0] * sc,
                                                    acc[mt][nt][h * 2 + 1] * sc);
            }
        }
}

// ---------------------------------------------------------------------------
// Merged fp32 -> fp16 rounding for all 4 inputs. grid.y selects the tensor.
// ---------------------------------------------------------------------------
__global__ void split_all_kernel(const float* __restrict__ x,
                                 const float* __restrict__ wq,
                                 const float* __restrict__ wk,
                                 const float* __restrict__ wv,
                                 h16* __restrict__ xo, h16* __restrict__ qo,
                                 h16* __restrict__ ko, h16* __restrict__ vo)
{
    const int a = blockIdx.y;
    const float* s = (a == 0) ? x : (a == 1) ? wq : (a == 2) ? wk : wv;
    h16* d        = (a == 0) ? xo : (a == 1) ? qo : (a == 2) ? ko : vo;
    const int n   = (a == 0) ? BATCH * SEQ * EMB : DIM * EMB;

    const int i = (blockIdx.x * blockDim.x + threadIdx.x) * 8;
    if (i >= n) return;
    const float4 p = *(const float4*)(s + i);
    const float4 q = *(const float4*)(s + i + 4);
    __half2 h0 = __floats2half2_rn(p.x, p.y);
    __half2 h1 = __floats2half2_rn(p.z, p.w);
    __half2 h2 = __floats2half2_rn(q.x, q.y);
    __half2 h3 = __floats2half2_rn(q.z, q.w);
    uint4 o;
    o.x = *(uint32_t*)&h0; o.y = *(uint32_t*)&h1;
    o.z = *(uint32_t*)&h2; o.w = *(uint32_t*)&h3;
    *(uint4*)(d + i) = o;
}

// ---------------------------------------------------------------------------
// Causal softmax: fp32 scores (k<=q valid) -> attn fp16. Longest rows first.
// ---------------------------------------------------------------------------
__global__ void softmax_kernel(const float* __restrict__ S,
                               h16* __restrict__ Phi)
{
    const int row = (int)(gridDim.x - 1 - blockIdx.x);   // heavy rows first
    const int b = row >> 11;
    const int q = row & 2047;
    const float* sr = S + ((size_t)b * SEQ + q) * SEQ;
    const size_t ob = ((size_t)b * SEQ + q) * SEQ;
    const int len  = q + 1;
    const int klim = ((q >> 7) + 1) << 7;

    __shared__ float buf[SEQ];
    __shared__ float red[8];

    float m = -1e30f;
    const int len4 = len & ~3;
    for (int k = threadIdx.x * 4; k < len4; k += blockDim.x * 4) {
        const float4 v = *(const float4*)(sr + k);
        *(float4*)(buf + k) = v;
        m = fmaxf(m, fmaxf(fmaxf(v.x, v.y), fmaxf(v.z, v.w)));
    }
    for (int k = len4 + threadIdx.x; k < len; k += blockDim.x) {
        const float v = sr[k];
        buf[k] = v;
        m = fmaxf(m, v);
    }
#pragma unroll
    for (int o = 16; o; o >>= 1)
        m = fmaxf(m, __shfl_xor_sync(0xffffffffu, m, o));
    if ((threadIdx.x & 31) == 0) red[threadIdx.x >> 5] = m;
    __syncthreads();
    m = red[0];
#pragma unroll
    for (int w = 1; w < 8; ++w) m = fmaxf(m, red[w]);

    float sum = 0.f;
    for (int k = threadIdx.x; k < len; k += blockDim.x) {
        const float e = __expf(buf[k] - m);
        buf[k] = e;
        sum += e;
    }
#pragma unroll
    for (int o = 16; o; o >>= 1)
        sum += __shfl_xor_sync(0xffffffffu, sum, o);
    __syncthreads();
    if ((threadIdx.x & 31) == 0) red[threadIdx.x >> 5] = sum;
    __syncthreads();
    sum = 0.f;
#pragma unroll
    for (int w = 0; w < 8; ++w) sum += red[w];

    const float inv = 1.0f / sum;

    for (int k = threadIdx.x * 8; k < klim; k += blockDim.x * 8) {
        __half2 h[4];
#pragma unroll
        for (int j = 0; j < 4; ++j) {
            const int k0 = k + j * 2;
            const float a0 = (k0     < len) ? buf[k0]     * inv : 0.f;
            const float a1 = (k0 + 1 < len) ? buf[k0 + 1] * inv : 0.f;
            h[j] = __floats2half2_rn(a0, a1);
        }
        uint4 o;
        o.x = *(uint32_t*)&h[0]; o.y = *(uint32_t*)&h[1];
        o.z = *(uint32_t*)&h[2]; o.w = *(uint32_t*)&h[3];
        *(uint4*)(Phi + ob + k) = o;
    }
}

// ---------------------------------------------------------------------------
extern "C" void kernel_launch(void* const* d_in, const int* in_sizes, int n_in,
                              void* d_out, int out_size)
{
    const float* x  = (const float*)d_in[0];
    const float* Wk = (const float*)d_in[1];
    const float* Wq = (const float*)d_in[2];
    const float* Wv = (const float*)d_in[3];
    float* out = (float*)d_out;

    h16 *xhi, *wqh, *wkh, *wvh;
    h16 *qhi, *khi, *vthi, *phi;
    float* s;
    cudaGetSymbolAddress((void**)&xhi,  g_xhi);
    cudaGetSymbolAddress((void**)&wqh,  g_Wqhi);
    cudaGetSymbolAddress((void**)&wkh,  g_Wkhi);
    cudaGetSymbolAddress((void**)&wvh,  g_Wvhi);
    cudaGetSymbolAddress((void**)&qhi,  g_Qhi);
    cudaGetSymbolAddress((void**)&khi,  g_Khi);
    cudaGetSymbolAddress((void**)&vthi, g_Vthi);
    cudaGetSymbolAddress((void**)&phi,  g_Phi);
    cudaGetSymbolAddress((void**)&s,    g_S);

    cudaFuncSetAttribute((const void*)proj_gemm,    cudaFuncAttributeMaxDynamicSharedMemorySize, SMEM_BYTES);
    cudaFuncSetAttribute((const void*)attn_gemm<2>, cudaFuncAttributeMaxDynamicSharedMemorySize, SMEM_BYTES);
    cudaFuncSetAttribute((const void*)attn_gemm<3>, cudaFuncAttributeMaxDynamicSharedMemorySize, SMEM_BYTES);

    const float inv_scale = 1.0f / sqrtf((float)DIM);

    // Side stream + events for overlapping the V projection with the
    // scores/softmax chain. Created per call (host objects only; no device
    // memory). Not destroyed to avoid interacting with an active capture.
    cudaStream_t s2;
    cudaStreamCreateWithFlags(&s2, cudaStreamNonBlocking);
    cudaEvent_t eSplit, eV;
    cudaEventCreateWithFlags(&eSplit, cudaEventDisableTiming);
    cudaEventCreateWithFlags(&eV,     cudaEventDisableTiming);

    {
        dim3 gs((BATCH * SEQ * EMB / 8 + 255) / 256, 4);
        split_all_kernel<<<gs, 256>>>(x, Wq, Wk, Wv, xhi, wqh, wkh, wvh);
    }
    cudaEventRecord(eSplit, 0);
    cudaStreamWaitEvent(s2, eSplit, 0);

    dim3 blk(256);

    // V projection on the side stream (independent of scores/softmax)
    dim3 gv(DIM / 128, (BATCH * SEQ) / 128, 1);
    proj_gemm<<<gv, blk, SMEM_BYTES, s2>>>(xhi, wqh, wkh, wvh, qhi, khi, vthi, 2);

    // Q + K projections on the main stream
    dim3 gqk(DIM / 128, (BATCH * SEQ) / 128, 2);
    proj_gemm<<<gqk, blk, SMEM_BYTES>>>(xhi, wqh, wkh, wvh, qhi, khi, vthi, 0);

    dim3 gattn(SEQ / 128, SEQ / 128, BATCH);            // 16 x 16 x 4
    attn_gemm<2><<<gattn, blk, SMEM_BYTES>>>(qhi, khi, s, inv_scale);

    softmax_kernel<<<BATCH * SEQ, 256>>>(s, phi);

    // AV needs softmax (stream order) AND V^T (event join)
    cudaEventRecord(eV, s2);
    cudaStreamWaitEvent(0, eV, 0);
    attn_gemm<3><<<gattn, blk, SMEM_BYTES>>>(phi, vthi, out, 0.f);
}

// round 16
// speedup vs baseline: 6.6412x; 1.0155x over previous
#include <cuda_runtime.h>
#include <cuda_fp16.h>
#include <math.h>
#include <stdint.h>

#define SEQ   2048
#define EMB   2048
#define DIM   2048
#define BATCH 4

typedef __half h16;

// ---------------------------------------------------------------------------
// Device scratch (no cudaMalloc allowed anywhere)
// ---------------------------------------------------------------------------
__device__ h16 g_xhi[(size_t)BATCH * SEQ * EMB];
__device__ h16 g_Wqhi[(size_t)DIM * EMB];
__device__ h16 g_Wkhi[(size_t)DIM * EMB];
__device__ h16 g_Wvhi[(size_t)DIM * EMB];
__device__ h16 g_Qhi[(size_t)BATCH * SEQ * DIM];
__device__ h16 g_Khi[(size_t)BATCH * SEQ * DIM];
__device__ h16 g_Vthi[(size_t)BATCH * DIM * SEQ];   // V^T per batch
__device__ float g_S [(size_t)BATCH * SEQ * SEQ];
__device__ h16 g_Phi[(size_t)BATCH * SEQ * SEQ];

// ---------------------------------------------------------------------------
// PTX helpers (sm_80-level PTX only; no arch-suffixed instructions)
// ---------------------------------------------------------------------------
__device__ __forceinline__ uint32_t smem_u32(const void* p) {
    uint32_t a;
    asm("{ .reg .u64 t; cvta.to.shared.u64 t, %1; cvt.u32.u64 %0, t; }"
        : "=r"(a) : "l"(p));
    return a;
}

__device__ __forceinline__ void cp16(uint32_t dst, const void* src) {
    asm volatile("cp.async.cg.shared.global [%0], [%1], 16;" :: "r"(dst), "l"(src));
}
__device__ __forceinline__ void cp_commit() {
    asm volatile("cp.async.commit_group;" ::: "memory");
}
template<int N> __device__ __forceinline__ void cp_wait() {
    asm volatile("cp.async.wait_group %0;" :: "n"(N) : "memory");
}

__device__ __forceinline__ void ldm4(uint32_t& r0, uint32_t& r1, uint32_t& r2,
                                     uint32_t& r3, uint32_t addr) {
    asm volatile("ldmatrix.sync.aligned.m8n8.x4.shared.b16 {%0,%1,%2,%3}, [%4];"
                 : "=r"(r0), "=r"(r1), "=r"(r2), "=r"(r3) : "r"(addr));
}

__device__ __forceinline__ void mma16816(float* c, const uint32_t* a,
                                         uint32_t b0, uint32_t b1) {
    asm volatile(
        "mma.sync.aligned.m16n8k16.row.col.f32.f16.f16.f32 "
        "{%0,%1,%2,%3}, {%4,%5,%6,%7}, {%8,%9}, {%0,%1,%2,%3};"
        : "+f"(c[0]), "+f"(c[1]), "+f"(c[2]), "+f"(c[3])
        : "r"(a[0]), "r"(a[1]), "r"(a[2]), "r"(a[3]), "r"(b0), "r"(b1));
}

// ---------------------------------------------------------------------------
// Tiling constants
// ---------------------------------------------------------------------------
#define ROWB 80                     // smem row stride bytes (32 h16 = 64B data + 16B pad)
#define TILEB (128 * ROWB)          // 10240 B per 128x32 tile
#define STG   (2 * TILEB)           // A, B per stage (1-pass fp16)
#define NSTAGE 5                    // ring depth (single-barrier-per-chunk safe)
static constexpr unsigned SMEM_BYTES = NSTAGE * STG;   // 102400; >= 34816 epilogue stage

// ---------------------------------------------------------------------------
// Shared GEMM mainloop (C = A @ B^T, K-major ld 2048).
// 5-deep cp.async ring, prefetch distance 3, ONE barrier per 32-K chunk.
// Chunk body: ALL 12 LDSM up front (A both halves, B half0, B half1), then
// 32 HMMA — half1 frag loads lead their first use by ~16 MMAs, removing the
// mid-chunk dependency bubble. Per-accumulator MMA order unchanged.
// ---------------------------------------------------------------------------
__device__ __forceinline__ void gemm_mainloop(
    const h16* __restrict__ Ah, const h16* __restrict__ Bh,
    uint32_t sbase, int nk, int tid, int lane, int warp_m, int warp_n,
    float acc[2][8][4])
{
    const int lrow = tid >> 2;
    const int lcb  = (tid & 3) * 16;

    auto load_stage = [&](int kc) {
        const uint32_t sd = sbase + (uint32_t)(kc % NSTAGE) * STG;
        const size_t goff = (size_t)kc * 32;
        const char* pa = (const char*)(Ah + goff);
        const char* pb = (const char*)(Bh + goff);
#pragma unroll
        for (int i = 0; i < 2; ++i) {
            const int r = lrow + i * 64;
            const uint32_t so = (uint32_t)r * ROWB + lcb;
            const size_t go = (size_t)r * 4096 + lcb;
            cp16(sd + so,         pa + go);
            cp16(sd + TILEB + so, pb + go);
        }
        cp_commit();
    };

    load_stage(0);
    load_stage(1);
    load_stage(2);

    const uint32_t lrh = (uint32_t)(lane & 15) * ROWB + (uint32_t)(lane >> 4) * 16;
    const uint32_t aoff = (uint32_t)(warp_m * 32) * ROWB + lrh;
    const uint32_t boff = (uint32_t)TILEB + (uint32_t)(warp_n * 64) * ROWB + lrh;

    for (int s = 0; s < nk; ++s) {
        if (s + 3 < nk) load_stage(s + 3);
        else            cp_commit();          // empty group keeps wait count aligned
        cp_wait<3>();
        __syncthreads();

        const uint32_t sd = sbase + (uint32_t)(s % NSTAGE) * STG;

        // ---- all fragment loads for the 32-K chunk, issued back-to-back ----
        uint32_t ah[2][2][4];     // [half][mt][reg]
        uint32_t bf[2][4][4];     // [half][g][reg]
#pragma unroll
        for (int half = 0; half < 2; ++half)
#pragma unroll
            for (int mt = 0; mt < 2; ++mt) {
                const uint32_t ro = sd + aoff + (uint32_t)(mt * 16) * ROWB
                                  + (uint32_t)half * 32;
                ldm4(ah[half][mt][0], ah[half][mt][1],
                     ah[half][mt][2], ah[half][mt][3], ro);
            }
#pragma unroll
        for (int half = 0; half < 2; ++half)
#pragma unroll
            for (int g = 0; g < 4; ++g) {
                const uint32_t ro = sd + boff + (uint32_t)(g * 16) * ROWB
                                  + (uint32_t)half * 32;
                ldm4(bf[half][g][0], bf[half][g][1],
                     bf[half][g][2], bf[half][g][3], ro);
            }

        // ---- 32 HMMA; per-accumulator order: half0 then half1 (unchanged) ----
#pragma unroll
        for (int half = 0; half < 2; ++half)
#pragma unroll
            for (int mt = 0; mt < 2; ++mt)
#pragma unroll
                for (int nt = 0; nt < 8; ++nt) {
                    const int g = nt >> 1, o = nt & 1;
                    mma16816(acc[mt][nt], ah[half][mt],
                             bf[half][g][o], bf[half][g][2 + o]);
                }
    }
    __syncthreads();   // protect smem reuse by epilogue staging
}

// ---------------------------------------------------------------------------
// QKV projection kernel. z = blockIdx.z + zbase selects W / output / mode.
//   z=0: Q row-major, z=1: K row-major, z=2: V transposed (smem-staged)
// ---------------------------------------------------------------------------
__global__ __launch_bounds__(256, 2)
void proj_gemm(const h16* __restrict__ x,
               const h16* __restrict__ wq, const h16* __restrict__ wk,
               const h16* __restrict__ wv,
               h16* __restrict__ qo, h16* __restrict__ ko, h16* __restrict__ vto,
               int zbase)
{
    const int bx = blockIdx.x, by = blockIdx.y;
    const int z  = (int)blockIdx.z + zbase;

    extern __shared__ char smem[];
    const uint32_t sbase = smem_u32(smem);

    const int tid    = threadIdx.x;
    const int wid    = tid >> 5;
    const int lane   = tid & 31;
    const int warp_m = wid & 3;
    const int warp_n = wid >> 2;

    const h16* Bw = (z == 0) ? wq : (z == 1) ? wk : wv;
    h16* out = (z == 0) ? qo : (z == 1) ? ko : vto;

    const h16* Ah = x  + (size_t)(by * 128) * 2048;
    const h16* Bh = Bw + (size_t)(bx * 128) * 2048;

    float acc[2][8][4] = {};
    gemm_mainloop(Ah, Bh, sbase, 64, tid, lane, warp_m, warp_n, acc);

    const int tq = lane >> 2;
    const int tr = lane & 3;

    if (z == 2) {
        // stage tile in smem, coalesced transposed write (V^T)
#pragma unroll
        for (int mt = 0; mt < 2; ++mt)
#pragma unroll
            for (int nt = 0; nt < 8; ++nt) {
                const int ml = warp_m * 32 + mt * 16 + tq;
                const int nl = warp_n * 64 + nt * 8 + tr * 2;
#pragma unroll
                for (int h = 0; h < 2; ++h) {
                    const float c0 = acc[mt][nt][h * 2 + 0];
                    const float c1 = acc[mt][nt][h * 2 + 1];
                    const uint32_t so = (uint32_t)(ml + h * 8) * 272 + (uint32_t)nl * 2;
                    *(__half2*)(smem + so) =
                        __halves2half2(__float2half_rn(c0), __float2half_rn(c1));
                }
            }
        __syncthreads();
        const int b   = by >> 4;
        const int st0 = (by & 15) * 128;
        const int nl  = tid >> 1;
        const int hh  = tid & 1;
        const size_t obase = ((size_t)b * 2048 + bx * 128 + nl) * 2048 + st0 + hh * 64;
#pragma unroll 4
        for (int j = 0; j < 64; j += 2) {
            const uint32_t s0 = (uint32_t)(hh * 64 + j) * 272 + (uint32_t)nl * 2;
            h16 a0 = *(const h16*)(smem + s0);
            h16 a1 = *(const h16*)(smem + s0 + 272);
            *(__half2*)(out + obase + j) = __halves2half2(a0, a1);
        }
        return;
    }

#pragma unroll
    for (int mt = 0; mt < 2; ++mt)
#pragma unroll
        for (int nt = 0; nt < 8; ++nt) {
            const int gm = by * 128 + warp_m * 32 + mt * 16 + tq;
            const int gn = bx * 128 + warp_n * 64 + nt * 8 + tr * 2;
#pragma unroll
            for (int h = 0; h < 2; ++h) {
                const size_t o = (size_t)(gm + h * 8) * 2048 + gn;
                *(__half2*)(out + o) = __halves2half2(
                    __float2half_rn(acc[mt][nt][h * 2 + 0]),
                    __float2half_rn(acc[mt][nt][h * 2 + 1]));
            }
        }
}

// ---------------------------------------------------------------------------
// Attention GEMMs. Heavy-first remap: by = 15 - blockIdx.y.
//   MODE 2: scores -> fp32 * scale, causal tile skip
//   MODE 3: attn @ V^T -> fp32, causal K bound
// ---------------------------------------------------------------------------
template<int MODE>
__global__ __launch_bounds__(256, 2)
void attn_gemm(const h16* __restrict__ Ahi, const h16* __restrict__ Bhi,
               float* __restrict__ out_f, float scale)
{
    const int bx = blockIdx.x;
    const int by = (int)(gridDim.y - 1 - blockIdx.y);   // heavy tiles first
    const int bz = blockIdx.z;
    if (MODE == 2 && bx > by) return;

    extern __shared__ char smem[];
    const uint32_t sbase = smem_u32(smem);

    const int tid    = threadIdx.x;
    const int wid    = tid >> 5;
    const int lane   = tid & 31;
    const int warp_m = wid & 3;
    const int warp_n = wid >> 2;

    const size_t boff = (size_t)bz * 2048 * 2048;
    const h16* Ah = Ahi + boff + (size_t)(by * 128) * 2048;
    const h16* Bh = Bhi + boff + (size_t)(bx * 128) * 2048;

    const int nk = (MODE == 3) ? (by + 1) * 4 : 64;

    float acc[2][8][4] = {};
    gemm_mainloop(Ah, Bh, sbase, nk, tid, lane, warp_m, warp_n, acc);

    const int tq = lane >> 2;
    const int tr = lane & 3;
    const float sc = (MODE == 2) ? scale : 1.0f;

#pragma unroll
    for (int mt = 0; mt < 2; ++mt)
#pragma unroll
        for (int nt = 0; nt < 8; ++nt) {
            const int gm = by * 128 + warp_m * 32 + mt * 16 + tq;
            const int gn = bx * 128 + warp_n * 64 + nt * 8 + tr * 2;
#pragma unroll
            for (int h = 0; h < 2; ++h) {
                const size_t o = boff + (size_t)(gm + h * 8) * 2048 + gn;
                *(float2*)(out_f + o) = make_float2(acc[mt][nt][h * 2 + 0] * sc,
                                                    acc[mt][nt][h * 2 + 1] * sc);
            }
        }
}

// ---------------------------------------------------------------------------
// Merged fp32 -> fp16 rounding for all 4 inputs. grid.y selects the tensor.
// ---------------------------------------------------------------------------
__global__ void split_all_kernel(const float* __restrict__ x,
                                 const float* __restrict__ wq,
                                 const float* __restrict__ wk,
                                 const float* __restrict__ wv,
                                 h16* __restrict__ xo, h16* __restrict__ qo,
                                 h16* __restrict__ ko, h16* __restrict__ vo)
{
    const int a = blockIdx.y;
    const float* s = (a == 0) ? x : (a == 1) ? wq : (a == 2) ? wk : wv;
    h16* d        = (a == 0) ? xo : (a == 1) ? qo : (a == 2) ? ko : vo;
    const int n   = (a == 0) ? BATCH * SEQ * EMB : DIM * EMB;

    const int i = (blockIdx.x * blockDim.x + threadIdx.x) * 8;
    if (i >= n) return;
    const float4 p = *(const float4*)(s + i);
    const float4 q = *(const float4*)(s + i + 4);
    __half2 h0 = __floats2half2_rn(p.x, p.y);
    __half2 h1 = __floats2half2_rn(p.z, p.w);
    __half2 h2 = __floats2half2_rn(q.x, q.y);
    __half2 h3 = __floats2half2_rn(q.z, q.w);
    uint4 o;
    o.x = *(uint32_t*)&h0; o.y = *(uint32_t*)&h1;
    o.z = *(uint32_t*)&h2; o.w = *(uint32_t*)&h3;
    *(uint4*)(d + i) = o;
}

// ---------------------------------------------------------------------------
// Causal softmax: fp32 scores (k<=q valid) -> attn fp16. Longest rows first.
// ---------------------------------------------------------------------------
__global__ void softmax_kernel(const float* __restrict__ S,
                               h16* __restrict__ Phi)
{
    const int row = (int)(gridDim.x - 1 - blockIdx.x);   // heavy rows first
    const int b = row >> 11;
    const int q = row & 2047;
    const float* sr = S + ((size_t)b * SEQ + q) * SEQ;
    const size_t ob = ((size_t)b * SEQ + q) * SEQ;
    const int len  = q + 1;
    const int klim = ((q >> 7) + 1) << 7;

    __shared__ float buf[SEQ];
    __shared__ float red[8];

    float m = -1e30f;
    const int len4 = len & ~3;
    for (int k = threadIdx.x * 4; k < len4; k += blockDim.x * 4) {
        const float4 v = *(const float4*)(sr + k);
        *(float4*)(buf + k) = v;
        m = fmaxf(m, fmaxf(fmaxf(v.x, v.y), fmaxf(v.z, v.w)));
    }
    for (int k = len4 + threadIdx.x; k < len; k += blockDim.x) {
        const float v = sr[k];
        buf[k] = v;
        m = fmaxf(m, v);
    }
#pragma unroll
    for (int o = 16; o; o >>= 1)
        m = fmaxf(m, __shfl_xor_sync(0xffffffffu, m, o));
    if ((threadIdx.x & 31) == 0) red[threadIdx.x >> 5] = m;
    __syncthreads();
    m = red[0];
#pragma unroll
    for (int w = 1; w < 8; ++w) m = fmaxf(m, red[w]);

    float sum = 0.f;
    for (int k = threadIdx.x; k < len; k += blockDim.x) {
        const float e = __expf(buf[k] - m);
        buf[k] = e;
        sum += e;
    }
#pragma unroll
    for (int o = 16; o; o >>= 1)
        sum += __shfl_xor_sync(0xffffffffu, sum, o);
    __syncthreads();
    if ((threadIdx.x & 31) == 0) red[threadIdx.x >> 5] = sum;
    __syncthreads();
    sum = 0.f;
#pragma unroll
    for (int w = 0; w < 8; ++w) sum += red[w];

    const float inv = 1.0f / sum;

    for (int k = threadIdx.x * 8; k < klim; k += blockDim.x * 8) {
        __half2 h[4];
#pragma unroll
        for (int j = 0; j < 4; ++j) {
            const int k0 = k + j * 2;
            const float a0 = (k0     < len) ? buf[k0]     * inv : 0.f;
            const float a1 = (k0 + 1 < len) ? buf[k0 + 1] * inv : 0.f;
            h[j] = __floats2half2_rn(a0, a1);
        }
        uint4 o;
        o.x = *(uint32_t*)&h[0]; o.y = *(uint32_t*)&h[1];
        o.z = *(uint32_t*)&h[2]; o.w = *(uint32_t*)&h[3];
        *(uint4*)(Phi + ob + k) = o;
    }
}

// ---------------------------------------------------------------------------
extern "C" void kernel_launch(void* const* d_in, const int* in_sizes, int n_in,
                              void* d_out, int out_size)
{
    const float* x  = (const float*)d_in[0];
    const float* Wk = (const float*)d_in[1];
    const float* Wq = (const float*)d_in[2];
    const float* Wv = (const float*)d_in[3];
    float* out = (float*)d_out;

    h16 *xhi, *wqh, *wkh, *wvh;
    h16 *qhi, *khi, *vthi, *phi;
    float* s;
    cudaGetSymbolAddress((void**)&xhi,  g_xhi);
    cudaGetSymbolAddress((void**)&wqh,  g_Wqhi);
    cudaGetSymbolAddress((void**)&wkh,  g_Wkhi);
    cudaGetSymbolAddress((void**)&wvh,  g_Wvhi);
    cudaGetSymbolAddress((void**)&qhi,  g_Qhi);
    cudaGetSymbolAddress((void**)&khi,  g_Khi);
    cudaGetSymbolAddress((void**)&vthi, g_Vthi);
    cudaGetSymbolAddress((void**)&phi,  g_Phi);
    cudaGetSymbolAddress((void**)&s,    g_S);

    cudaFuncSetAttribute((const void*)proj_gemm,    cudaFuncAttributeMaxDynamicSharedMemorySize, SMEM_BYTES);
    cudaFuncSetAttribute((const void*)attn_gemm<2>, cudaFuncAttributeMaxDynamicSharedMemorySize, SMEM_BYTES);
    cudaFuncSetAttribute((const void*)attn_gemm<3>, cudaFuncAttributeMaxDynamicSharedMemorySize, SMEM_BYTES);

    const float inv_scale = 1.0f / sqrtf((float)DIM);

    // Side stream + events (verified graph-capturable in R15).
    cudaStream_t s2;
    cudaStreamCreateWithFlags(&s2, cudaStreamNonBlocking);
    cudaEvent_t eSplit, eV;
    cudaEventCreateWithFlags(&eSplit, cudaEventDisableTiming);
    cudaEventCreateWithFlags(&eV,     cudaEventDisableTiming);

    {
        dim3 gs((BATCH * SEQ * EMB / 8 + 255) / 256, 4);
        split_all_kernel<<<gs, 256>>>(x, Wq, Wk, Wv, xhi, wqh, wkh, wvh);
    }
    cudaEventRecord(eSplit, 0);
    cudaStreamWaitEvent(s2, eSplit, 0);

    dim3 blk(256);

    // V projection on the side stream (independent of scores/softmax)
    dim3 gv(DIM / 128, (BATCH * SEQ) / 128, 1);
    proj_gemm<<<gv, blk, SMEM_BYTES, s2>>>(xhi, wqh, wkh, wvh, qhi, khi, vthi, 2);

    // Q + K projections on the main stream
    dim3 gqk(DIM / 128, (BATCH * SEQ) / 128, 2);
    proj_gemm<<<gqk, blk, SMEM_BYTES>>>(xhi, wqh, wkh, wvh, qhi, khi, vthi, 0);

    dim3 gattn(SEQ / 128, SEQ / 128, BATCH);            // 16 x 16 x 4
    attn_gemm<2><<<gattn, blk, SMEM_BYTES>>>(qhi, khi, s, inv_scale);

    softmax_kernel<<<BATCH * SEQ, 256>>>(s, phi);

    // AV needs softmax (stream order) AND V^T (event join)
    cudaEventRecord(eV, s2);
    cudaStreamWaitEvent(0, eV, 0);
    attn_gemm<3><<<gattn, blk, SMEM_BYTES>>>(phi, vthi, out, 0.f);
}